// round 7
// baseline (speedup 1.0000x reference)
#include <cuda_runtime.h>
#include <stdint.h>
#include <math.h>

// ============================================================
// ROUND 7: FIX — never pass __device__ symbols as kernel args
// from host (on GB300/ATS they silently resolve to the HOST
// shadow copy via NVLink-C2C; decoder was reading zeros).
// All global scratch is referenced directly inside kernels.
// Pipeline otherwise identical to R5 (dense all-experts,
// reference-exact weights).
// ============================================================

// Problem constants
#define NB   16384      // batch
#define DD   512        // dim
#define NL   6          // streams
#define NCLS 3992       // output classes
#define NE   4          // experts

// -------- device scratch (no allocations allowed) --------
__device__ float g_logits[NB * NE];
__device__ float g_w[NB * NE];
__device__ float g_h [NE * NB * DD];   // per-expert layer1 relu output
__device__ float g_eo[NE * NB * DD];   // per-expert layer2 output
__device__ float g_s[NB * DD];         // mixed "selected"
__device__ float g_t[NB * DD];         // sigmoid(dec layer1)

// ============================================================
// K1: gate logits (one warp per row), plain fp32
// ============================================================
__global__ __launch_bounds__(128) void gate_kernel(const float* __restrict__ fusion,
                                                   const float* __restrict__ gW,
                                                   const float* __restrict__ gb) {
    int warp = blockIdx.x * (blockDim.x >> 5) + (threadIdx.x >> 5);
    int lane = threadIdx.x & 31;
    if (warp >= NB) return;
    int b = warp;
    float a0 = 0.f, a1 = 0.f, a2 = 0.f, a3 = 0.f;
    for (int k = lane; k < NL * DD; k += 32) {
        int l = k >> 9;
        int d = k & 511;
        float xv = fusion[((size_t)l * NB + b) * DD + d];
        float4 w = *(const float4*)(gW + (size_t)k * 4);
        a0 += xv * w.x; a1 += xv * w.y; a2 += xv * w.z; a3 += xv * w.w;
    }
#pragma unroll
    for (int o = 16; o; o >>= 1) {
        a0 += __shfl_down_sync(0xffffffffu, a0, o);
        a1 += __shfl_down_sync(0xffffffffu, a1, o);
        a2 += __shfl_down_sync(0xffffffffu, a2, o);
        a3 += __shfl_down_sync(0xffffffffu, a3, o);
    }
    if (lane == 0) {
        g_logits[b * 4 + 0] = a0 + gb[0];
        g_logits[b * 4 + 1] = a1 + gb[1];
        g_logits[b * 4 + 2] = a2 + gb[2];
        g_logits[b * 4 + 3] = a3 + gb[3];
    }
}

// ============================================================
// K1b: weight = soft + (hard - soft)  (reference-exact)
// ============================================================
__global__ void weight_kernel() {
    int b = blockIdx.x * blockDim.x + threadIdx.x;
    if (b >= NB) return;
    float l0 = g_logits[b * 4 + 0];
    float l1 = g_logits[b * 4 + 1];
    float l2 = g_logits[b * 4 + 2];
    float l3 = g_logits[b * 4 + 3];
    float m = fmaxf(fmaxf(l0, l1), fmaxf(l2, l3));
    float e0 = expf(l0 - m), e1 = expf(l1 - m), e2 = expf(l2 - m), e3 = expf(l3 - m);
    float s = e0 + e1 + e2 + e3;
    float s0 = e0 / s, s1 = e1 / s, s2 = e2 / s, s3 = e3 / s;
    int am = 0; float best = l0;
    if (l1 > best) { best = l1; am = 1; }
    if (l2 > best) { best = l2; am = 2; }
    if (l3 > best) { best = l3; am = 3; }
    float h0 = (am == 0) ? 1.f : 0.f;
    float h1 = (am == 1) ? 1.f : 0.f;
    float h2 = (am == 2) ? 1.f : 0.f;
    float h3 = (am == 3) ? 1.f : 0.f;
    g_w[b * 4 + 0] = s0 + (h0 - s0);
    g_w[b * 4 + 1] = s1 + (h1 - s1);
    g_w[b * 4 + 2] = s2 + (h2 - s2);
    g_w[b * 4 + 3] = s3 + (h3 - s3);
}

// ============================================================
// GEMM tile params: 64x64 tile, TK=16, 256 threads, 4x4 microtile
// ============================================================
#define TB 64
#define TN 64
#define TK 16

// ============================================================
// K2: DENSE expert layer1 for all rows, all experts
//   g_h[e] = relu(x_e @ W1_e + b1_e)     (writes g_h directly)
// ============================================================
__global__ __launch_bounds__(256) void expertL1_kernel(
    const float* __restrict__ fusion,
    const float* W10, const float* W11, const float* W12, const float* W13,
    const float* b10, const float* b11, const float* b12, const float* b13,
    const float* pa, const float* pb) {

    int e = blockIdx.z;
    const float* W1s[4] = { W10, W11, W12, W13 };
    const float* b1s[4] = { b10, b11, b12, b13 };
    const int    Ks[4]  = { 3 * DD, 3 * DD, 6 * DD, 6 * DD };
    const int    Bs[4]  = { 0, 3, 0, 0 };

    const float* W1 = W1s[e];
    const float* b1 = b1s[e];
    int K    = Ks[e];
    int base = Bs[e];
    float sa = (e == 3) ? *pa : 1.0f;
    float sb = (e == 3) ? *pb : 1.0f;

    __shared__ float As[TK][TB];
    __shared__ float Ws[TK][TN];

    int tid = threadIdx.x;
    int row0 = blockIdx.x * TB;
    int col0 = blockIdx.y * TN;
    int tr = tid >> 4, tc = tid & 15;
    float acc[4][4];
#pragma unroll
    for (int i = 0; i < 4; i++)
#pragma unroll
        for (int j = 0; j < 4; j++) acc[i][j] = 0.f;

    int arr = tid >> 2;
    int akq = (tid & 3) * 4;

    for (int kc = 0; kc < K; kc += TK) {
        {
            int row = row0 + arr;
            int kg = kc + akq;
            int lraw = kg >> 9;
            int l = lraw + base;
            int d = kg & 511;
            float4 v = *(const float4*)(fusion + ((size_t)l * NB + row) * DD + d);
            float s = (lraw < 3) ? sa : sb;
            As[akq + 0][arr] = v.x * s;
            As[akq + 1][arr] = v.y * s;
            As[akq + 2][arr] = v.z * s;
            As[akq + 3][arr] = v.w * s;
        }
#pragma unroll
        for (int t = 0; t < 4; t++) {
            int li = tid + t * 256;
            int kk = li >> 6, cc = li & 63;
            Ws[kk][cc] = W1[(size_t)(kc + kk) * DD + col0 + cc];
        }
        __syncthreads();

#pragma unroll
        for (int kk = 0; kk < TK; kk++) {
            float af[4], bf[4];
#pragma unroll
            for (int i = 0; i < 4; i++) af[i] = As[kk][tr * 4 + i];
#pragma unroll
            for (int j = 0; j < 4; j++) bf[j] = Ws[kk][tc * 4 + j];
#pragma unroll
            for (int i = 0; i < 4; i++)
#pragma unroll
                for (int j = 0; j < 4; j++) acc[i][j] += af[i] * bf[j];
        }
        __syncthreads();
    }

    float* outp = g_h + (size_t)e * NB * DD;
#pragma unroll
    for (int i = 0; i < 4; i++) {
        int row = row0 + tr * 4 + i;
#pragma unroll
        for (int j = 0; j < 4; j++) {
            int c = col0 + tc * 4 + j;
            float v = acc[i][j] + b1[c];
            outp[(size_t)row * DD + c] = v > 0.f ? v : 0.f;
        }
    }
}

// ============================================================
// K3: DENSE expert layer2 (reads g_h, writes g_eo directly)
// ============================================================
__global__ __launch_bounds__(256) void expertL2_kernel(
    const float* W20, const float* W21, const float* W22, const float* W23,
    const float* b20, const float* b21, const float* b22, const float* b23) {

    int e = blockIdx.z;
    const float* W2s[4] = { W20, W21, W22, W23 };
    const float* b2s[4] = { b20, b21, b22, b23 };
    const float* W2 = W2s[e];
    const float* b2 = b2s[e];
    const float* A  = g_h + (size_t)e * NB * DD;

    __shared__ float As[TK][TB];
    __shared__ float Ws[TK][TN];

    int tid = threadIdx.x;
    int row0 = blockIdx.x * TB;
    int col0 = blockIdx.y * TN;
    int tr = tid >> 4, tc = tid & 15;
    float acc[4][4];
#pragma unroll
    for (int i = 0; i < 4; i++)
#pragma unroll
        for (int j = 0; j < 4; j++) acc[i][j] = 0.f;

    int arr = tid >> 2;
    int akq = (tid & 3) * 4;

    for (int kc = 0; kc < DD; kc += TK) {
        {
            int row = row0 + arr;
            float4 v = *(const float4*)(A + (size_t)row * DD + kc + akq);
            As[akq + 0][arr] = v.x;
            As[akq + 1][arr] = v.y;
            As[akq + 2][arr] = v.z;
            As[akq + 3][arr] = v.w;
        }
#pragma unroll
        for (int t = 0; t < 4; t++) {
            int li = tid + t * 256;
            int kk = li >> 6, cc = li & 63;
            Ws[kk][cc] = W2[(size_t)(kc + kk) * DD + col0 + cc];
        }
        __syncthreads();

#pragma unroll
        for (int kk = 0; kk < TK; kk++) {
            float af[4], bf[4];
#pragma unroll
            for (int i = 0; i < 4; i++) af[i] = As[kk][tr * 4 + i];
#pragma unroll
            for (int j = 0; j < 4; j++) bf[j] = Ws[kk][tc * 4 + j];
#pragma unroll
            for (int i = 0; i < 4; i++)
#pragma unroll
                for (int j = 0; j < 4; j++) acc[i][j] += af[i] * bf[j];
        }
        __syncthreads();
    }

    float* outp = g_eo + (size_t)e * NB * DD;
#pragma unroll
    for (int i = 0; i < 4; i++) {
        int row = row0 + tr * 4 + i;
#pragma unroll
        for (int j = 0; j < 4; j++) {
            int c = col0 + tc * 4 + j;
            outp[(size_t)row * DD + c] = acc[i][j] + b2[c];
        }
    }
}

// ============================================================
// K3b: mix  g_s[b,d] = sum_i w[b,i] * g_eo[i,b,d]
// ============================================================
__global__ void mix_kernel() {
    size_t idx = (size_t)blockIdx.x * blockDim.x + threadIdx.x;
    if (idx >= (size_t)NB * DD) return;
    int b = (int)(idx >> 9);
    float w0 = g_w[b * 4 + 0];
    float w1 = g_w[b * 4 + 1];
    float w2 = g_w[b * 4 + 2];
    float w3 = g_w[b * 4 + 3];
    const size_t S = (size_t)NB * DD;
    float v = w0 * g_eo[idx];
    v = fmaf(w1, g_eo[S + idx], v);
    v = fmaf(w2, g_eo[2 * S + idx], v);
    v = fmaf(w3, g_eo[3 * S + idx], v);
    g_s[idx] = v;
}

// ============================================================
// K4: decoder layer1 + sigmoid (reads g_s, writes g_t — both
//     referenced DIRECTLY inside the kernel)
// ============================================================
__global__ __launch_bounds__(256) void dec1_kernel(
    const float* __restrict__ W, const float* __restrict__ bias) {

    int row0 = blockIdx.x * TB;
    int col0 = blockIdx.y * TN;

    __shared__ float As[TK][TB];
    __shared__ float Ws[TK][TN];

    int tid = threadIdx.x;
    int tr = tid >> 4, tc = tid & 15;
    float acc[4][4];
#pragma unroll
    for (int i = 0; i < 4; i++)
#pragma unroll
        for (int j = 0; j < 4; j++) acc[i][j] = 0.f;

    int arr = tid >> 2;
    int akq = (tid & 3) * 4;

    for (int kc = 0; kc < DD; kc += TK) {
        {
            int row = row0 + arr;
            float4 v = *(const float4*)(g_s + (size_t)row * DD + kc + akq);
            As[akq + 0][arr] = v.x;
            As[akq + 1][arr] = v.y;
            As[akq + 2][arr] = v.z;
            As[akq + 3][arr] = v.w;
        }
#pragma unroll
        for (int t = 0; t < 4; t++) {
            int li = tid + t * 256;
            int kk = li >> 6, cc = li & 63;
            Ws[kk][cc] = W[(size_t)(kc + kk) * DD + col0 + cc];
        }
        __syncthreads();

#pragma unroll
        for (int kk = 0; kk < TK; kk++) {
            float af[4], bf[4];
#pragma unroll
            for (int i = 0; i < 4; i++) af[i] = As[kk][tr * 4 + i];
#pragma unroll
            for (int j = 0; j < 4; j++) bf[j] = Ws[kk][tc * 4 + j];
#pragma unroll
            for (int i = 0; i < 4; i++)
#pragma unroll
                for (int j = 0; j < 4; j++) acc[i][j] += af[i] * bf[j];
        }
        __syncthreads();
    }

#pragma unroll
    for (int i = 0; i < 4; i++) {
        int row = row0 + tr * 4 + i;
#pragma unroll
        for (int j = 0; j < 4; j++) {
            int c = col0 + tc * 4 + j;
            float v = acc[i][j] + bias[c];
            g_t[(size_t)row * DD + c] = 1.f / (1.f + expf(-v));
        }
    }
}

// ============================================================
// K5: decoder layer2 (reads g_t directly, writes harness d_out)
// ============================================================
__global__ __launch_bounds__(256) void dec2_kernel(
    const float* __restrict__ W, const float* __restrict__ bias,
    float* __restrict__ out) {

    int row0 = blockIdx.x * TB;
    int col0 = blockIdx.y * TN;

    __shared__ float As[TK][TB];
    __shared__ float Ws[TK][TN];

    int tid = threadIdx.x;
    int tr = tid >> 4, tc = tid & 15;
    float acc[4][4];
#pragma unroll
    for (int i = 0; i < 4; i++)
#pragma unroll
        for (int j = 0; j < 4; j++) acc[i][j] = 0.f;

    int arr = tid >> 2;
    int akq = (tid & 3) * 4;

    for (int kc = 0; kc < DD; kc += TK) {
        {
            int row = row0 + arr;
            float4 v = *(const float4*)(g_t + (size_t)row * DD + kc + akq);
            As[akq + 0][arr] = v.x;
            As[akq + 1][arr] = v.y;
            As[akq + 2][arr] = v.z;
            As[akq + 3][arr] = v.w;
        }
#pragma unroll
        for (int t = 0; t < 4; t++) {
            int li = tid + t * 256;
            int kk = li >> 6, cc = li & 63;
            int c = col0 + cc;
            Ws[kk][cc] = (c < NCLS) ? W[(size_t)(kc + kk) * NCLS + c] : 0.f;
        }
        __syncthreads();

#pragma unroll
        for (int kk = 0; kk < TK; kk++) {
            float af[4], bf[4];
#pragma unroll
            for (int i = 0; i < 4; i++) af[i] = As[kk][tr * 4 + i];
#pragma unroll
            for (int j = 0; j < 4; j++) bf[j] = Ws[kk][tc * 4 + j];
#pragma unroll
            for (int i = 0; i < 4; i++)
#pragma unroll
                for (int j = 0; j < 4; j++) acc[i][j] += af[i] * bf[j];
        }
        __syncthreads();
    }

#pragma unroll
    for (int i = 0; i < 4; i++) {
        int row = row0 + tr * 4 + i;
#pragma unroll
        for (int j = 0; j < 4; j++) {
            int c = col0 + tc * 4 + j;
            if (c < NCLS)
                out[(size_t)row * NCLS + c] = acc[i][j] + bias[c];
        }
    }
}

// ============================================================
// launch  (only harness pointers cross the launch boundary)
// ============================================================
extern "C" void kernel_launch(void* const* d_in, const int* in_sizes, int n_in,
                              void* d_out, int out_size) {
    const float* fusion = (const float*)d_in[0];
    const float* gate_W = (const float*)d_in[1];
    const float* gate_b = (const float*)d_in[2];
    const float* e0_W1  = (const float*)d_in[3];
    const float* e0_b1  = (const float*)d_in[4];
    const float* e0_W2  = (const float*)d_in[5];
    const float* e0_b2  = (const float*)d_in[6];
    const float* e1_W1  = (const float*)d_in[7];
    const float* e1_b1  = (const float*)d_in[8];
    const float* e1_W2  = (const float*)d_in[9];
    const float* e1_b2  = (const float*)d_in[10];
    const float* e2_W1  = (const float*)d_in[11];
    const float* e2_b1  = (const float*)d_in[12];
    const float* e2_W2  = (const float*)d_in[13];
    const float* e2_b2  = (const float*)d_in[14];
    const float* e3_W1  = (const float*)d_in[15];
    const float* e3_b1  = (const float*)d_in[16];
    const float* e3_W2  = (const float*)d_in[17];
    const float* e3_b2  = (const float*)d_in[18];
    const float* e3_a   = (const float*)d_in[19];
    const float* e3_b   = (const float*)d_in[20];
    const float* dec_W1 = (const float*)d_in[21];
    const float* dec_b1 = (const float*)d_in[22];
    const float* dec_W2 = (const float*)d_in[23];
    const float* dec_b2 = (const float*)d_in[24];
    float* out = (float*)d_out;

    // K1: gate logits
    gate_kernel<<<NB / 4, 128>>>(fusion, gate_W, gate_b);

    // K1b: reference-exact weights
    weight_kernel<<<NB / 256, 256>>>();

    // K2: dense expert layer1 (all rows x all experts)
    {
        dim3 grid(NB / TB, DD / TN, NE);
        expertL1_kernel<<<grid, 256>>>(fusion,
            e0_W1, e1_W1, e2_W1, e3_W1,
            e0_b1, e1_b1, e2_b1, e3_b1,
            e3_a, e3_b);
    }

    // K3: dense expert layer2
    {
        dim3 grid(NB / TB, DD / TN, NE);
        expertL2_kernel<<<grid, 256>>>(
            e0_W2, e1_W2, e2_W2, e3_W2,
            e0_b2, e1_b2, e2_b2, e3_b2);
    }

    // K3b: mixture
    {
        size_t total = (size_t)NB * DD;
        mix_kernel<<<(unsigned)((total + 255) / 256), 256>>>();
    }

    // K4: decoder layer1 + sigmoid
    {
        dim3 grid(NB / TB, DD / TN);
        dec1_kernel<<<grid, 256>>>(dec_W1, dec_b1);
    }

    // K5: decoder layer2 -> output
    {
        dim3 grid(NB / TB, (NCLS + TN - 1) / TN);
        dec2_kernel<<<grid, 256>>>(dec_W2, dec_b2, out);
    }
}

// round 8
// speedup vs baseline: 2.2469x; 2.2469x over previous
#include <cuda_runtime.h>
#include <stdint.h>
#include <math.h>

// ============================================================
// ROUND 8: restore hard single-expert routing (forward uses only
// one-hot(argmax)) on top of the fixed decoder. All scratch is
// referenced directly inside kernels (GB300 ATS host-shadow rule:
// never pass __device__ symbols from host).
//   work: 265 -> 123 GFLOP; mix kernel + g_eo eliminated
//   (expert L2 scatters straight into g_s).
// ============================================================

// Problem constants
#define NB   16384      // batch
#define DD   512        // dim
#define NL   6          // streams
#define NCLS 3992       // output classes
#define NE   4          // experts

// -------- device scratch --------
__device__ float g_h[NB * DD];       // expert layer1 output (relu'd), compact rows
__device__ float g_s[NB * DD];       // selected (scattered to original rows)
__device__ float g_t[NB * DD];       // sigmoid(dec layer1)
__device__ int   g_sel[NB];
__device__ int   g_rows[NE * NB];
__device__ int   g_cnt[NE];

// ============================================================
// K1: gate logits + argmax (one warp per row), exact fp32.
// Routing must be exact: a single flipped row costs ~2e-3 rel_err.
// ============================================================
__global__ __launch_bounds__(128) void gate_kernel(const float* __restrict__ fusion,
                                                   const float* __restrict__ gW,
                                                   const float* __restrict__ gb) {
    int warp = blockIdx.x * (blockDim.x >> 5) + (threadIdx.x >> 5);
    int lane = threadIdx.x & 31;
    if (warp >= NB) return;
    int b = warp;
    float a0 = 0.f, a1 = 0.f, a2 = 0.f, a3 = 0.f;
    for (int k = lane; k < NL * DD; k += 32) {
        int l = k >> 9;
        int d = k & 511;
        float xv = fusion[((size_t)l * NB + b) * DD + d];
        float4 w = *(const float4*)(gW + (size_t)k * 4);
        a0 += xv * w.x; a1 += xv * w.y; a2 += xv * w.z; a3 += xv * w.w;
    }
#pragma unroll
    for (int o = 16; o; o >>= 1) {
        a0 += __shfl_down_sync(0xffffffffu, a0, o);
        a1 += __shfl_down_sync(0xffffffffu, a1, o);
        a2 += __shfl_down_sync(0xffffffffu, a2, o);
        a3 += __shfl_down_sync(0xffffffffu, a3, o);
    }
    if (lane == 0) {
        a0 += gb[0]; a1 += gb[1]; a2 += gb[2]; a3 += gb[3];
        int bi = 0; float best = a0;               // first-max (matches jnp.argmax)
        if (a1 > best) { best = a1; bi = 1; }
        if (a2 > best) { best = a2; bi = 2; }
        if (a3 > best) { best = a3; bi = 3; }
        g_sel[b] = bi;
    }
}

// ============================================================
// K1b: zero counters; compact rows per expert
// ============================================================
__global__ void zero_cnt_kernel() {
    if (threadIdx.x < NE) g_cnt[threadIdx.x] = 0;
}

__global__ void compact_kernel() {
    int b = blockIdx.x * blockDim.x + threadIdx.x;
    if (b < NB) {
        int e = g_sel[b];
        int i = atomicAdd(&g_cnt[e], 1);
        g_rows[e * NB + i] = b;
    }
}

// ============================================================
// GEMM tile params: 64x64 tile, TK=16, 256 threads, 4x4 microtile
// ============================================================
#define TB 64
#define TN 64
#define TK 16

// ============================================================
// K2: routed expert layer1 (gathered rows from fusion)
//   g_h[compact r, :] = relu(x_e[row r] @ W1_e + b1_e)
//   g_h is indexed by COMPACT position (e-segment order), so K3
//   reads it contiguously; scatter to original rows happens in K3.
// ============================================================
__global__ __launch_bounds__(256) void expert1_kernel(
    const float* __restrict__ fusion,
    const float* W10, const float* W11, const float* W12, const float* W13,
    const float* b10, const float* b11, const float* b12, const float* b13,
    const float* pa, const float* pb) {

    int e = blockIdx.z;
    int cnt = g_cnt[e];
    int row0 = blockIdx.x * TB;
    if (row0 >= cnt) return;

    // segment base in the compact ordering = sum of counts of lower experts
    int seg = 0;
#pragma unroll
    for (int q = 0; q < NE; q++) if (q < e) seg += g_cnt[q];

    const float* W1s[4] = { W10, W11, W12, W13 };
    const float* b1s[4] = { b10, b11, b12, b13 };
    const int    Ks[4]  = { 3 * DD, 3 * DD, 6 * DD, 6 * DD };
    const int    Bs[4]  = { 0, 3, 0, 0 };

    const float* W1 = W1s[e];
    const float* b1 = b1s[e];
    int K    = Ks[e];
    int base = Bs[e];
    float sa = (e == 3) ? *pa : 1.0f;
    float sb = (e == 3) ? *pb : 1.0f;

    __shared__ float As[TK][TB];
    __shared__ float Ws[TK][TN];
    __shared__ int   rowids[TB];

    int tid = threadIdx.x;
    if (tid < TB) {
        int r = row0 + tid;
        rowids[tid] = (r < cnt) ? g_rows[e * NB + r] : -1;
    }
    __syncthreads();

    int col0 = blockIdx.y * TN;
    int tr = tid >> 4, tc = tid & 15;
    float acc[4][4];
#pragma unroll
    for (int i = 0; i < 4; i++)
#pragma unroll
        for (int j = 0; j < 4; j++) acc[i][j] = 0.f;

    int arr = tid >> 2;
    int akq = (tid & 3) * 4;

    for (int kc = 0; kc < K; kc += TK) {
        {
            int row = rowids[arr];
            float4 v = make_float4(0.f, 0.f, 0.f, 0.f);
            if (row >= 0) {
                int kg = kc + akq;
                int lraw = kg >> 9;
                int l = lraw + base;
                int d = kg & 511;
                v = *(const float4*)(fusion + ((size_t)l * NB + row) * DD + d);
                float s = (lraw < 3) ? sa : sb;
                v.x *= s; v.y *= s; v.z *= s; v.w *= s;
            }
            As[akq + 0][arr] = v.x;
            As[akq + 1][arr] = v.y;
            As[akq + 2][arr] = v.z;
            As[akq + 3][arr] = v.w;
        }
#pragma unroll
        for (int t = 0; t < 4; t++) {
            int li = tid + t * 256;
            int kk = li >> 6, cc = li & 63;
            Ws[kk][cc] = W1[(size_t)(kc + kk) * DD + col0 + cc];
        }
        __syncthreads();

#pragma unroll
        for (int kk = 0; kk < TK; kk++) {
            float af[4], bf[4];
#pragma unroll
            for (int i = 0; i < 4; i++) af[i] = As[kk][tr * 4 + i];
#pragma unroll
            for (int j = 0; j < 4; j++) bf[j] = Ws[kk][tc * 4 + j];
#pragma unroll
            for (int i = 0; i < 4; i++)
#pragma unroll
                for (int j = 0; j < 4; j++) acc[i][j] += af[i] * bf[j];
        }
        __syncthreads();
    }

    // store at COMPACT position (seg + r) for contiguous K3 reads
#pragma unroll
    for (int i = 0; i < 4; i++) {
        int r = row0 + tr * 4 + i;
        if (r >= cnt) continue;
#pragma unroll
        for (int j = 0; j < 4; j++) {
            int c = col0 + tc * 4 + j;
            float v = acc[i][j] + b1[c];
            g_h[(size_t)(seg + r) * DD + c] = v > 0.f ? v : 0.f;
        }
    }
}

// ============================================================
// K3: routed expert layer2 — contiguous reads of compact g_h,
//     scatter result to g_s at the ORIGINAL row.
// ============================================================
__global__ __launch_bounds__(256) void expert2_kernel(
    const float* W20, const float* W21, const float* W22, const float* W23,
    const float* b20, const float* b21, const float* b22, const float* b23) {

    int e = blockIdx.z;
    int cnt = g_cnt[e];
    int row0 = blockIdx.x * TB;
    if (row0 >= cnt) return;

    int seg = 0;
#pragma unroll
    for (int q = 0; q < NE; q++) if (q < e) seg += g_cnt[q];

    const float* W2s[4] = { W20, W21, W22, W23 };
    const float* b2s[4] = { b20, b21, b22, b23 };
    const float* W2 = W2s[e];
    const float* b2 = b2s[e];

    __shared__ float As[TK][TB];
    __shared__ float Ws[TK][TN];
    __shared__ int   rowids[TB];

    int tid = threadIdx.x;
    if (tid < TB) {
        int r = row0 + tid;
        rowids[tid] = (r < cnt) ? g_rows[e * NB + r] : -1;
    }
    __syncthreads();

    int col0 = blockIdx.y * TN;
    int tr = tid >> 4, tc = tid & 15;
    float acc[4][4];
#pragma unroll
    for (int i = 0; i < 4; i++)
#pragma unroll
        for (int j = 0; j < 4; j++) acc[i][j] = 0.f;

    int arr = tid >> 2;
    int akq = (tid & 3) * 4;

    for (int kc = 0; kc < DD; kc += TK) {
        {
            int r = row0 + arr;
            float4 v = make_float4(0.f, 0.f, 0.f, 0.f);
            if (r < cnt)
                v = *(const float4*)(g_h + (size_t)(seg + r) * DD + kc + akq);
            As[akq + 0][arr] = v.x;
            As[akq + 1][arr] = v.y;
            As[akq + 2][arr] = v.z;
            As[akq + 3][arr] = v.w;
        }
#pragma unroll
        for (int t = 0; t < 4; t++) {
            int li = tid + t * 256;
            int kk = li >> 6, cc = li & 63;
            Ws[kk][cc] = W2[(size_t)(kc + kk) * DD + col0 + cc];
        }
        __syncthreads();

#pragma unroll
        for (int kk = 0; kk < TK; kk++) {
            float af[4], bf[4];
#pragma unroll
            for (int i = 0; i < 4; i++) af[i] = As[kk][tr * 4 + i];
#pragma unroll
            for (int j = 0; j < 4; j++) bf[j] = Ws[kk][tc * 4 + j];
#pragma unroll
            for (int i = 0; i < 4; i++)
#pragma unroll
                for (int j = 0; j < 4; j++) acc[i][j] += af[i] * bf[j];
        }
        __syncthreads();
    }

#pragma unroll
    for (int i = 0; i < 4; i++) {
        int row = rowids[tr * 4 + i];
        if (row < 0) continue;
#pragma unroll
        for (int j = 0; j < 4; j++) {
            int c = col0 + tc * 4 + j;
            g_s[(size_t)row * DD + c] = acc[i][j] + b2[c];
        }
    }
}

// ============================================================
// K4: decoder layer1 + sigmoid (g_s -> g_t, direct global refs)
// ============================================================
__global__ __launch_bounds__(256) void dec1_kernel(
    const float* __restrict__ W, const float* __restrict__ bias) {

    int row0 = blockIdx.x * TB;
    int col0 = blockIdx.y * TN;

    __shared__ float As[TK][TB];
    __shared__ float Ws[TK][TN];

    int tid = threadIdx.x;
    int tr = tid >> 4, tc = tid & 15;
    float acc[4][4];
#pragma unroll
    for (int i = 0; i < 4; i++)
#pragma unroll
        for (int j = 0; j < 4; j++) acc[i][j] = 0.f;

    int arr = tid >> 2;
    int akq = (tid & 3) * 4;

    for (int kc = 0; kc < DD; kc += TK) {
        {
            int row = row0 + arr;
            float4 v = *(const float4*)(g_s + (size_t)row * DD + kc + akq);
            As[akq + 0][arr] = v.x;
            As[akq + 1][arr] = v.y;
            As[akq + 2][arr] = v.z;
            As[akq + 3][arr] = v.w;
        }
#pragma unroll
        for (int t = 0; t < 4; t++) {
            int li = tid + t * 256;
            int kk = li >> 6, cc = li & 63;
            Ws[kk][cc] = W[(size_t)(kc + kk) * DD + col0 + cc];
        }
        __syncthreads();

#pragma unroll
        for (int kk = 0; kk < TK; kk++) {
            float af[4], bf[4];
#pragma unroll
            for (int i = 0; i < 4; i++) af[i] = As[kk][tr * 4 + i];
#pragma unroll
            for (int j = 0; j < 4; j++) bf[j] = Ws[kk][tc * 4 + j];
#pragma unroll
            for (int i = 0; i < 4; i++)
#pragma unroll
                for (int j = 0; j < 4; j++) acc[i][j] += af[i] * bf[j];
        }
        __syncthreads();
    }

#pragma unroll
    for (int i = 0; i < 4; i++) {
        int row = row0 + tr * 4 + i;
#pragma unroll
        for (int j = 0; j < 4; j++) {
            int c = col0 + tc * 4 + j;
            float v = acc[i][j] + bias[c];
            g_t[(size_t)row * DD + c] = 1.f / (1.f + expf(-v));
        }
    }
}

// ============================================================
// K5: decoder layer2 (g_t -> harness out)
// ============================================================
__global__ __launch_bounds__(256) void dec2_kernel(
    const float* __restrict__ W, const float* __restrict__ bias,
    float* __restrict__ out) {

    int row0 = blockIdx.x * TB;
    int col0 = blockIdx.y * TN;

    __shared__ float As[TK][TB];
    __shared__ float Ws[TK][TN];

    int tid = threadIdx.x;
    int tr = tid >> 4, tc = tid & 15;
    float acc[4][4];
#pragma unroll
    for (int i = 0; i < 4; i++)
#pragma unroll
        for (int j = 0; j < 4; j++) acc[i][j] = 0.f;

    int arr = tid >> 2;
    int akq = (tid & 3) * 4;

    for (int kc = 0; kc < DD; kc += TK) {
        {
            int row = row0 + arr;
            float4 v = *(const float4*)(g_t + (size_t)row * DD + kc + akq);
            As[akq + 0][arr] = v.x;
            As[akq + 1][arr] = v.y;
            As[akq + 2][arr] = v.z;
            As[akq + 3][arr] = v.w;
        }
#pragma unroll
        for (int t = 0; t < 4; t++) {
            int li = tid + t * 256;
            int kk = li >> 6, cc = li & 63;
            int c = col0 + cc;
            Ws[kk][cc] = (c < NCLS) ? W[(size_t)(kc + kk) * NCLS + c] : 0.f;
        }
        __syncthreads();

#pragma unroll
        for (int kk = 0; kk < TK; kk++) {
            float af[4], bf[4];
#pragma unroll
            for (int i = 0; i < 4; i++) af[i] = As[kk][tr * 4 + i];
#pragma unroll
            for (int j = 0; j < 4; j++) bf[j] = Ws[kk][tc * 4 + j];
#pragma unroll
            for (int i = 0; i < 4; i++)
#pragma unroll
                for (int j = 0; j < 4; j++) acc[i][j] += af[i] * bf[j];
        }
        __syncthreads();
    }

#pragma unroll
    for (int i = 0; i < 4; i++) {
        int row = row0 + tr * 4 + i;
#pragma unroll
        for (int j = 0; j < 4; j++) {
            int c = col0 + tc * 4 + j;
            if (c < NCLS)
                out[(size_t)row * NCLS + c] = acc[i][j] + bias[c];
        }
    }
}

// ============================================================
// launch  (only harness pointers cross the launch boundary)
// ============================================================
extern "C" void kernel_launch(void* const* d_in, const int* in_sizes, int n_in,
                              void* d_out, int out_size) {
    const float* fusion = (const float*)d_in[0];
    const float* gate_W = (const float*)d_in[1];
    const float* gate_b = (const float*)d_in[2];
    const float* e0_W1  = (const float*)d_in[3];
    const float* e0_b1  = (const float*)d_in[4];
    const float* e0_W2  = (const float*)d_in[5];
    const float* e0_b2  = (const float*)d_in[6];
    const float* e1_W1  = (const float*)d_in[7];
    const float* e1_b1  = (const float*)d_in[8];
    const float* e1_W2  = (const float*)d_in[9];
    const float* e1_b2  = (const float*)d_in[10];
    const float* e2_W1  = (const float*)d_in[11];
    const float* e2_b1  = (const float*)d_in[12];
    const float* e2_W2  = (const float*)d_in[13];
    const float* e2_b2  = (const float*)d_in[14];
    const float* e3_W1  = (const float*)d_in[15];
    const float* e3_b1  = (const float*)d_in[16];
    const float* e3_W2  = (const float*)d_in[17];
    const float* e3_b2  = (const float*)d_in[18];
    const float* e3_a   = (const float*)d_in[19];
    const float* e3_b   = (const float*)d_in[20];
    const float* dec_W1 = (const float*)d_in[21];
    const float* dec_b1 = (const float*)d_in[22];
    const float* dec_W2 = (const float*)d_in[23];
    const float* dec_b2 = (const float*)d_in[24];
    float* out = (float*)d_out;

    // K1: gate argmax (exact fp32)
    gate_kernel<<<NB / 4, 128>>>(fusion, gate_W, gate_b);

    // K1b: compact rows by expert
    zero_cnt_kernel<<<1, 32>>>();
    compact_kernel<<<NB / 256, 256>>>();

    // K2: routed expert layer1 (gathered GEMM, relu)
    {
        dim3 grid(NB / TB, DD / TN, NE);
        expert1_kernel<<<grid, 256>>>(fusion,
            e0_W1, e1_W1, e2_W1, e3_W1,
            e0_b1, e1_b1, e2_b1, e3_b1,
            e3_a, e3_b);
    }

    // K3: routed expert layer2 (contiguous in, scatter out to g_s)
    {
        dim3 grid(NB / TB, DD / TN, NE);
        expert2_kernel<<<grid, 256>>>(
            e0_W2, e1_W2, e2_W2, e3_W2,
            e0_b2, e1_b2, e2_b2, e3_b2);
    }

    // K4: decoder layer1 + sigmoid
    {
        dim3 grid(NB / TB, DD / TN);
        dec1_kernel<<<grid, 256>>>(dec_W1, dec_b1);
    }

    // K5: decoder layer2 -> output
    {
        dim3 grid(NB / TB, (NCLS + TN - 1) / TN);
        dec2_kernel<<<grid, 256>>>(dec_W2, dec_b2, out);
    }
}

// round 9
// speedup vs baseline: 5.5685x; 2.4783x over previous
#include <cuda_runtime.h>
#include <stdint.h>
#include <math.h>

// ============================================================
// ROUND 9: tf32 tensor-core GEMMs (mma.sync.m16n8k8) for all 4
// GEMM stages; gate stays exact fp32 (routing must not flip).
// Mean-extraction on dec2 (g_t = 0.5 + delta; exact fp32 mean
// vector) kills the dominant tf32 error term.
// GB300 ATS rule: no __device__ symbol ever passed from host.
// ============================================================

#define NB   16384
#define DD   512
#define NL   6
#define NCLS 3992
#define NE   4

// GEMM tile
#define BM 128
#define BN 64
#define BK 32
#define ASTR 36     // As row stride (pad) -> conflict-free A frags
#define BSTR 72     // Bs row stride (pad) -> conflict-free B frags

// -------- device scratch --------
__device__ float g_h [NB * DD];      // expert L1 out (compact rows)
__device__ float g_s [NB * DD];      // selected (original rows)
__device__ float g_td[NB * DD];      // sigmoid(dec1) - 0.5
__device__ float g_mean[4096];       // 0.5*colsum(dec_W2)+dec_b2
__device__ int   g_sel[NB];
__device__ int   g_rows[NE * NB];
__device__ int   g_cnt[NE];

__device__ __forceinline__ unsigned f2tf(float x) {
    unsigned u;
    asm("cvt.rna.tf32.f32 %0, %1;" : "=r"(u) : "f"(x));
    return u;
}

#define MMA_TF32(c, a, b)                                                    \
    asm("mma.sync.aligned.m16n8k8.row.col.f32.tf32.tf32.f32 "                \
        "{%0,%1,%2,%3}, {%4,%5,%6,%7}, {%8,%9}, {%0,%1,%2,%3};"              \
        : "+f"((c)[0]), "+f"((c)[1]), "+f"((c)[2]), "+f"((c)[3])             \
        : "r"((a)[0]), "r"((a)[1]), "r"((a)[2]), "r"((a)[3]),                \
          "r"((b)[0]), "r"((b)[1]))

// ============================================================
// K1: gate logits + argmax (one warp per row), exact fp32
// ============================================================
__global__ __launch_bounds__(128) void gate_kernel(const float* __restrict__ fusion,
                                                   const float* __restrict__ gW,
                                                   const float* __restrict__ gb) {
    int warp = blockIdx.x * (blockDim.x >> 5) + (threadIdx.x >> 5);
    int lane = threadIdx.x & 31;
    if (warp >= NB) return;
    int b = warp;
    float a0 = 0.f, a1 = 0.f, a2 = 0.f, a3 = 0.f;
    for (int k = lane; k < NL * DD; k += 32) {
        int l = k >> 9;
        int d = k & 511;
        float xv = fusion[((size_t)l * NB + b) * DD + d];
        float4 w = *(const float4*)(gW + (size_t)k * 4);
        a0 += xv * w.x; a1 += xv * w.y; a2 += xv * w.z; a3 += xv * w.w;
    }
#pragma unroll
    for (int o = 16; o; o >>= 1) {
        a0 += __shfl_down_sync(0xffffffffu, a0, o);
        a1 += __shfl_down_sync(0xffffffffu, a1, o);
        a2 += __shfl_down_sync(0xffffffffu, a2, o);
        a3 += __shfl_down_sync(0xffffffffu, a3, o);
    }
    if (lane == 0) {
        a0 += gb[0]; a1 += gb[1]; a2 += gb[2]; a3 += gb[3];
        int bi = 0; float best = a0;
        if (a1 > best) { best = a1; bi = 1; }
        if (a2 > best) { best = a2; bi = 2; }
        if (a3 > best) { best = a3; bi = 3; }
        g_sel[b] = bi;
    }
}

__global__ void zero_cnt_kernel() {
    if (threadIdx.x < NE) g_cnt[threadIdx.x] = 0;
}

__global__ void compact_kernel() {
    int b = blockIdx.x * blockDim.x + threadIdx.x;
    if (b < NB) {
        int e = g_sel[b];
        int i = atomicAdd(&g_cnt[e], 1);
        g_rows[e * NB + i] = b;
    }
}

// exact fp32 mean vector: g_mean[c] = 0.5*sum_k W2[k][c] + b2[c]
__global__ void mean_kernel(const float* __restrict__ W, const float* __restrict__ b) {
    int c = blockIdx.x * blockDim.x + threadIdx.x;
    if (c >= NCLS) return;
    float s = 0.f;
#pragma unroll 8
    for (int k = 0; k < DD; k++) s += W[(size_t)k * NCLS + c];
    g_mean[c] = 0.5f * s + b[c];
}

// ============================================================
// K2: routed expert layer1, tf32 MMA
//   g_h[compact] = relu(x_e @ W1_e + b1_e)
// ============================================================
__global__ __launch_bounds__(256) void expert1_mma(
    const float* __restrict__ fusion,
    const float* W10, const float* W11, const float* W12, const float* W13,
    const float* b10, const float* b11, const float* b12, const float* b13,
    const float* pa, const float* pb) {

    int e = blockIdx.z;
    int cnt = g_cnt[e];
    int row0 = blockIdx.x * BM;
    if (row0 >= cnt) return;

    int seg = 0;
#pragma unroll
    for (int q = 0; q < NE; q++) if (q < e) seg += g_cnt[q];

    const float* W1s[4] = { W10, W11, W12, W13 };
    const float* b1s[4] = { b10, b11, b12, b13 };
    const int    Ks[4]  = { 3 * DD, 3 * DD, 6 * DD, 6 * DD };
    const int    Bs_[4] = { 0, 3, 0, 0 };
    const float* W1 = W1s[e];
    const float* b1 = b1s[e];
    int K    = Ks[e];
    int base = Bs_[e];
    float sa = (e == 3) ? *pa : 1.0f;
    float sb = (e == 3) ? *pb : 1.0f;

    __shared__ unsigned As[BM * ASTR];
    __shared__ unsigned Bs[BK * BSTR];
    __shared__ int rowids[BM];

    int tid = threadIdx.x;
    for (int i = tid; i < BM; i += 256) {
        int r = row0 + i;
        rowids[i] = (r < cnt) ? g_rows[e * NB + r] : -1;
    }
    __syncthreads();

    int col0 = blockIdx.y * BN;
    int wid = tid >> 5, lane = tid & 31, g = lane >> 2, tg = lane & 3;
    int warpM = (wid & 3) * 32, warpN = (wid >> 2) * 32;

    float acc[2][4][4];
#pragma unroll
    for (int mi = 0; mi < 2; mi++)
#pragma unroll
        for (int ni = 0; ni < 4; ni++)
#pragma unroll
            for (int k = 0; k < 4; k++) acc[mi][ni][k] = 0.f;

    for (int kc = 0; kc < K; kc += BK) {
#pragma unroll
        for (int t = 0; t < 4; t++) {
            int q = tid + t * 256;
            int ar = q >> 3, ak = (q & 7) * 4;
            int row = rowids[ar];
            float4 v = make_float4(0.f, 0.f, 0.f, 0.f);
            if (row >= 0) {
                int kg = kc + ak;
                int lraw = kg >> 9;
                int d = kg & 511;
                v = *(const float4*)(fusion + ((size_t)(lraw + base) * NB + row) * DD + d);
                float s = (lraw < 3) ? sa : sb;
                v.x *= s; v.y *= s; v.z *= s; v.w *= s;
            }
            unsigned* p = &As[ar * ASTR + ak];
            p[0] = f2tf(v.x); p[1] = f2tf(v.y); p[2] = f2tf(v.z); p[3] = f2tf(v.w);
        }
#pragma unroll
        for (int t = 0; t < 2; t++) {
            int q = tid + t * 256;
            int bk = q >> 4, bn = (q & 15) * 4;
            float4 v = *(const float4*)(W1 + (size_t)(kc + bk) * DD + col0 + bn);
            unsigned* p = &Bs[bk * BSTR + bn];
            p[0] = f2tf(v.x); p[1] = f2tf(v.y); p[2] = f2tf(v.z); p[3] = f2tf(v.w);
        }
        __syncthreads();

#pragma unroll
        for (int ks = 0; ks < 4; ks++) {
            unsigned a[2][4], b[4][2];
#pragma unroll
            for (int mi = 0; mi < 2; mi++) {
                int mb = warpM + mi * 16;
                a[mi][0] = As[(mb + g) * ASTR + ks * 8 + tg];
                a[mi][1] = As[(mb + g + 8) * ASTR + ks * 8 + tg];
                a[mi][2] = As[(mb + g) * ASTR + ks * 8 + tg + 4];
                a[mi][3] = As[(mb + g + 8) * ASTR + ks * 8 + tg + 4];
            }
#pragma unroll
            for (int ni = 0; ni < 4; ni++) {
                b[ni][0] = Bs[(ks * 8 + tg) * BSTR + warpN + ni * 8 + g];
                b[ni][1] = Bs[(ks * 8 + tg + 4) * BSTR + warpN + ni * 8 + g];
            }
#pragma unroll
            for (int mi = 0; mi < 2; mi++)
#pragma unroll
                for (int ni = 0; ni < 4; ni++)
                    MMA_TF32(acc[mi][ni], a[mi], b[ni]);
        }
        __syncthreads();
    }

#pragma unroll
    for (int mi = 0; mi < 2; mi++) {
        int ra = row0 + warpM + mi * 16 + g;
        int rb = ra + 8;
#pragma unroll
        for (int ni = 0; ni < 4; ni++) {
            int c0 = col0 + warpN + ni * 8 + tg * 2;
            int c1 = c0 + 1;
            float bb0 = b1[c0], bb1 = b1[c1];
            if (ra < cnt) {
                g_h[(size_t)(seg + ra) * DD + c0] = fmaxf(acc[mi][ni][0] + bb0, 0.f);
                g_h[(size_t)(seg + ra) * DD + c1] = fmaxf(acc[mi][ni][1] + bb1, 0.f);
            }
            if (rb < cnt) {
                g_h[(size_t)(seg + rb) * DD + c0] = fmaxf(acc[mi][ni][2] + bb0, 0.f);
                g_h[(size_t)(seg + rb) * DD + c1] = fmaxf(acc[mi][ni][3] + bb1, 0.f);
            }
        }
    }
}

// ============================================================
// K3: routed expert layer2, tf32 MMA; scatter to g_s
// ============================================================
__global__ __launch_bounds__(256) void expert2_mma(
    const float* W20, const float* W21, const float* W22, const float* W23,
    const float* b20, const float* b21, const float* b22, const float* b23) {

    int e = blockIdx.z;
    int cnt = g_cnt[e];
    int row0 = blockIdx.x * BM;
    if (row0 >= cnt) return;

    int seg = 0;
#pragma unroll
    for (int q = 0; q < NE; q++) if (q < e) seg += g_cnt[q];

    const float* W2s[4] = { W20, W21, W22, W23 };
    const float* b2s[4] = { b20, b21, b22, b23 };
    const float* W2 = W2s[e];
    const float* b2 = b2s[e];

    __shared__ unsigned As[BM * ASTR];
    __shared__ unsigned Bs[BK * BSTR];
    __shared__ int rowids[BM];

    int tid = threadIdx.x;
    for (int i = tid; i < BM; i += 256) {
        int r = row0 + i;
        rowids[i] = (r < cnt) ? g_rows[e * NB + r] : -1;
    }
    __syncthreads();

    int col0 = blockIdx.y * BN;
    int wid = tid >> 5, lane = tid & 31, g = lane >> 2, tg = lane & 3;
    int warpM = (wid & 3) * 32, warpN = (wid >> 2) * 32;

    float acc[2][4][4];
#pragma unroll
    for (int mi = 0; mi < 2; mi++)
#pragma unroll
        for (int ni = 0; ni < 4; ni++)
#pragma unroll
            for (int k = 0; k < 4; k++) acc[mi][ni][k] = 0.f;

    for (int kc = 0; kc < DD; kc += BK) {
#pragma unroll
        for (int t = 0; t < 4; t++) {
            int q = tid + t * 256;
            int ar = q >> 3, ak = (q & 7) * 4;
            float4 v = make_float4(0.f, 0.f, 0.f, 0.f);
            if (row0 + ar < cnt)
                v = *(const float4*)(g_h + (size_t)(seg + row0 + ar) * DD + kc + ak);
            unsigned* p = &As[ar * ASTR + ak];
            p[0] = f2tf(v.x); p[1] = f2tf(v.y); p[2] = f2tf(v.z); p[3] = f2tf(v.w);
        }
#pragma unroll
        for (int t = 0; t < 2; t++) {
            int q = tid + t * 256;
            int bk = q >> 4, bn = (q & 15) * 4;
            float4 v = *(const float4*)(W2 + (size_t)(kc + bk) * DD + col0 + bn);
            unsigned* p = &Bs[bk * BSTR + bn];
            p[0] = f2tf(v.x); p[1] = f2tf(v.y); p[2] = f2tf(v.z); p[3] = f2tf(v.w);
        }
        __syncthreads();

#pragma unroll
        for (int ks = 0; ks < 4; ks++) {
            unsigned a[2][4], b[4][2];
#pragma unroll
            for (int mi = 0; mi < 2; mi++) {
                int mb = warpM + mi * 16;
                a[mi][0] = As[(mb + g) * ASTR + ks * 8 + tg];
                a[mi][1] = As[(mb + g + 8) * ASTR + ks * 8 + tg];
                a[mi][2] = As[(mb + g) * ASTR + ks * 8 + tg + 4];
                a[mi][3] = As[(mb + g + 8) * ASTR + ks * 8 + tg + 4];
            }
#pragma unroll
            for (int ni = 0; ni < 4; ni++) {
                b[ni][0] = Bs[(ks * 8 + tg) * BSTR + warpN + ni * 8 + g];
                b[ni][1] = Bs[(ks * 8 + tg + 4) * BSTR + warpN + ni * 8 + g];
            }
#pragma unroll
            for (int mi = 0; mi < 2; mi++)
#pragma unroll
                for (int ni = 0; ni < 4; ni++)
                    MMA_TF32(acc[mi][ni], a[mi], b[ni]);
        }
        __syncthreads();
    }

#pragma unroll
    for (int mi = 0; mi < 2; mi++) {
        int la = warpM + mi * 16 + g;
        int lb = la + 8;
        int rowa = rowids[la];
        int rowb = rowids[lb];
#pragma unroll
        for (int ni = 0; ni < 4; ni++) {
            int c0 = col0 + warpN + ni * 8 + tg * 2;
            int c1 = c0 + 1;
            float bb0 = b2[c0], bb1 = b2[c1];
            if (rowa >= 0) {
                g_s[(size_t)rowa * DD + c0] = acc[mi][ni][0] + bb0;
                g_s[(size_t)rowa * DD + c1] = acc[mi][ni][1] + bb1;
            }
            if (rowb >= 0) {
                g_s[(size_t)rowb * DD + c0] = acc[mi][ni][2] + bb0;
                g_s[(size_t)rowb * DD + c1] = acc[mi][ni][3] + bb1;
            }
        }
    }
}

// ============================================================
// K4: decoder layer1, tf32 MMA; store sigmoid(z) - 0.5
// ============================================================
__global__ __launch_bounds__(256) void dec1_mma(
    const float* __restrict__ W, const float* __restrict__ bias) {

    int row0 = blockIdx.x * BM;
    int col0 = blockIdx.y * BN;

    __shared__ unsigned As[BM * ASTR];
    __shared__ unsigned Bs[BK * BSTR];

    int tid = threadIdx.x;
    int wid = tid >> 5, lane = tid & 31, g = lane >> 2, tg = lane & 3;
    int warpM = (wid & 3) * 32, warpN = (wid >> 2) * 32;

    float acc[2][4][4];
#pragma unroll
    for (int mi = 0; mi < 2; mi++)
#pragma unroll
        for (int ni = 0; ni < 4; ni++)
#pragma unroll
            for (int k = 0; k < 4; k++) acc[mi][ni][k] = 0.f;

    for (int kc = 0; kc < DD; kc += BK) {
#pragma unroll
        for (int t = 0; t < 4; t++) {
            int q = tid + t * 256;
            int ar = q >> 3, ak = (q & 7) * 4;
            float4 v = *(const float4*)(g_s + (size_t)(row0 + ar) * DD + kc + ak);
            unsigned* p = &As[ar * ASTR + ak];
            p[0] = f2tf(v.x); p[1] = f2tf(v.y); p[2] = f2tf(v.z); p[3] = f2tf(v.w);
        }
#pragma unroll
        for (int t = 0; t < 2; t++) {
            int q = tid + t * 256;
            int bk = q >> 4, bn = (q & 15) * 4;
            float4 v = *(const float4*)(W + (size_t)(kc + bk) * DD + col0 + bn);
            unsigned* p = &Bs[bk * BSTR + bn];
            p[0] = f2tf(v.x); p[1] = f2tf(v.y); p[2] = f2tf(v.z); p[3] = f2tf(v.w);
        }
        __syncthreads();

#pragma unroll
        for (int ks = 0; ks < 4; ks++) {
            unsigned a[2][4], b[4][2];
#pragma unroll
            for (int mi = 0; mi < 2; mi++) {
                int mb = warpM + mi * 16;
                a[mi][0] = As[(mb + g) * ASTR + ks * 8 + tg];
                a[mi][1] = As[(mb + g + 8) * ASTR + ks * 8 + tg];
                a[mi][2] = As[(mb + g) * ASTR + ks * 8 + tg + 4];
                a[mi][3] = As[(mb + g + 8) * ASTR + ks * 8 + tg + 4];
            }
#pragma unroll
            for (int ni = 0; ni < 4; ni++) {
                b[ni][0] = Bs[(ks * 8 + tg) * BSTR + warpN + ni * 8 + g];
                b[ni][1] = Bs[(ks * 8 + tg + 4) * BSTR + warpN + ni * 8 + g];
            }
#pragma unroll
            for (int mi = 0; mi < 2; mi++)
#pragma unroll
                for (int ni = 0; ni < 4; ni++)
                    MMA_TF32(acc[mi][ni], a[mi], b[ni]);
        }
        __syncthreads();
    }

#pragma unroll
    for (int mi = 0; mi < 2; mi++) {
        int ra = row0 + warpM + mi * 16 + g;
        int rb = ra + 8;
#pragma unroll
        for (int ni = 0; ni < 4; ni++) {
            int c0 = col0 + warpN + ni * 8 + tg * 2;
            int c1 = c0 + 1;
            float bb0 = bias[c0], bb1 = bias[c1];
            float z;
            z = acc[mi][ni][0] + bb0; g_td[(size_t)ra * DD + c0] = 1.f / (1.f + expf(-z)) - 0.5f;
            z = acc[mi][ni][1] + bb1; g_td[(size_t)ra * DD + c1] = 1.f / (1.f + expf(-z)) - 0.5f;
            z = acc[mi][ni][2] + bb0; g_td[(size_t)rb * DD + c0] = 1.f / (1.f + expf(-z)) - 0.5f;
            z = acc[mi][ni][3] + bb1; g_td[(size_t)rb * DD + c1] = 1.f / (1.f + expf(-z)) - 0.5f;
        }
    }
}

// ============================================================
// K5: decoder layer2, tf32 MMA on delta; out = acc + mean[c]
// ============================================================
__global__ __launch_bounds__(256) void dec2_mma(
    const float* __restrict__ W, float* __restrict__ out) {

    int row0 = blockIdx.x * BM;
    int col0 = blockIdx.y * BN;

    __shared__ unsigned As[BM * ASTR];
    __shared__ unsigned Bs[BK * BSTR];

    int tid = threadIdx.x;
    int wid = tid >> 5, lane = tid & 31, g = lane >> 2, tg = lane & 3;
    int warpM = (wid & 3) * 32, warpN = (wid >> 2) * 32;

    float acc[2][4][4];
#pragma unroll
    for (int mi = 0; mi < 2; mi++)
#pragma unroll
        for (int ni = 0; ni < 4; ni++)
#pragma unroll
            for (int k = 0; k < 4; k++) acc[mi][ni][k] = 0.f;

    for (int kc = 0; kc < DD; kc += BK) {
#pragma unroll
        for (int t = 0; t < 4; t++) {
            int q = tid + t * 256;
            int ar = q >> 3, ak = (q & 7) * 4;
            float4 v = *(const float4*)(g_td + (size_t)(row0 + ar) * DD + kc + ak);
            unsigned* p = &As[ar * ASTR + ak];
            p[0] = f2tf(v.x); p[1] = f2tf(v.y); p[2] = f2tf(v.z); p[3] = f2tf(v.w);
        }
#pragma unroll
        for (int t = 0; t < 2; t++) {
            int q = tid + t * 256;
            int bk = q >> 4, bn = (q & 15) * 4;
            int c = col0 + bn;
            float4 v = make_float4(0.f, 0.f, 0.f, 0.f);
            if (c + 3 < NCLS) {
                v = *(const float4*)(W + (size_t)(kc + bk) * NCLS + c);
            } else {
                float tmp[4];
#pragma unroll
                for (int i = 0; i < 4; i++)
                    tmp[i] = (c + i < NCLS) ? W[(size_t)(kc + bk) * NCLS + c + i] : 0.f;
                v.x = tmp[0]; v.y = tmp[1]; v.z = tmp[2]; v.w = tmp[3];
            }
            unsigned* p = &Bs[bk * BSTR + bn];
            p[0] = f2tf(v.x); p[1] = f2tf(v.y); p[2] = f2tf(v.z); p[3] = f2tf(v.w);
        }
        __syncthreads();

#pragma unroll
        for (int ks = 0; ks < 4; ks++) {
            unsigned a[2][4], b[4][2];
#pragma unroll
            for (int mi = 0; mi < 2; mi++) {
                int mb = warpM + mi * 16;
                a[mi][0] = As[(mb + g) * ASTR + ks * 8 + tg];
                a[mi][1] = As[(mb + g + 8) * ASTR + ks * 8 + tg];
                a[mi][2] = As[(mb + g) * ASTR + ks * 8 + tg + 4];
                a[mi][3] = As[(mb + g + 8) * ASTR + ks * 8 + tg + 4];
            }
#pragma unroll
            for (int ni = 0; ni < 4; ni++) {
                b[ni][0] = Bs[(ks * 8 + tg) * BSTR + warpN + ni * 8 + g];
                b[ni][1] = Bs[(ks * 8 + tg + 4) * BSTR + warpN + ni * 8 + g];
            }
#pragma unroll
            for (int mi = 0; mi < 2; mi++)
#pragma unroll
                for (int ni = 0; ni < 4; ni++)
                    MMA_TF32(acc[mi][ni], a[mi], b[ni]);
        }
        __syncthreads();
    }

#pragma unroll
    for (int mi = 0; mi < 2; mi++) {
        int ra = row0 + warpM + mi * 16 + g;
        int rb = ra + 8;
#pragma unroll
        for (int ni = 0; ni < 4; ni++) {
            int c0 = col0 + warpN + ni * 8 + tg * 2;
            int c1 = c0 + 1;
            if (c0 < NCLS) {
                float m0 = g_mean[c0];
                out[(size_t)ra * NCLS + c0] = acc[mi][ni][0] + m0;
                out[(size_t)rb * NCLS + c0] = acc[mi][ni][2] + m0;
            }
            if (c1 < NCLS) {
                float m1 = g_mean[c1];
                out[(size_t)ra * NCLS + c1] = acc[mi][ni][1] + m1;
                out[(size_t)rb * NCLS + c1] = acc[mi][ni][3] + m1;
            }
        }
    }
}

// ============================================================
// launch
// ============================================================
extern "C" void kernel_launch(void* const* d_in, const int* in_sizes, int n_in,
                              void* d_out, int out_size) {
    const float* fusion = (const float*)d_in[0];
    const float* gate_W = (const float*)d_in[1];
    const float* gate_b = (const float*)d_in[2];
    const float* e0_W1  = (const float*)d_in[3];
    const float* e0_b1  = (const float*)d_in[4];
    const float* e0_W2  = (const float*)d_in[5];
    const float* e0_b2  = (const float*)d_in[6];
    const float* e1_W1  = (const float*)d_in[7];
    const float* e1_b1  = (const float*)d_in[8];
    const float* e1_W2  = (const float*)d_in[9];
    const float* e1_b2  = (const float*)d_in[10];
    const float* e2_W1  = (const float*)d_in[11];
    const float* e2_b1  = (const float*)d_in[12];
    const float* e2_W2  = (const float*)d_in[13];
    const float* e2_b2  = (const float*)d_in[14];
    const float* e3_W1  = (const float*)d_in[15];
    const float* e3_b1  = (const float*)d_in[16];
    const float* e3_W2  = (const float*)d_in[17];
    const float* e3_b2  = (const float*)d_in[18];
    const float* e3_a   = (const float*)d_in[19];
    const float* e3_b   = (const float*)d_in[20];
    const float* dec_W1 = (const float*)d_in[21];
    const float* dec_b1 = (const float*)d_in[22];
    const float* dec_W2 = (const float*)d_in[23];
    const float* dec_b2 = (const float*)d_in[24];
    float* out = (float*)d_out;

    gate_kernel<<<NB / 4, 128>>>(fusion, gate_W, gate_b);
    zero_cnt_kernel<<<1, 32>>>();
    compact_kernel<<<NB / 256, 256>>>();
    mean_kernel<<<(NCLS + 255) / 256, 256>>>(dec_W2, dec_b2);

    {
        dim3 grid(NB / BM, DD / BN, NE);
        expert1_mma<<<grid, 256>>>(fusion,
            e0_W1, e1_W1, e2_W1, e3_W1,
            e0_b1, e1_b1, e2_b1, e3_b1,
            e3_a, e3_b);
    }
    {
        dim3 grid(NB / BM, DD / BN, NE);
        expert2_mma<<<grid, 256>>>(
            e0_W2, e1_W2, e2_W2, e3_W2,
            e0_b2, e1_b2, e2_b2, e3_b2);
    }
    {
        dim3 grid(NB / BM, DD / BN);
        dec1_mma<<<grid, 256>>>(dec_W1, dec_b1);
    }
    {
        dim3 grid(NB / BM, (NCLS + BN - 1) / BN);
        dec2_mma<<<grid, 256>>>(dec_W2, out);
    }
}

// round 10
// speedup vs baseline: 9.1066x; 1.6354x over previous
#include <cuda_runtime.h>
#include <stdint.h>
#include <math.h>

// ============================================================
// ROUND 10: cp.async double-buffered tf32 MMA GEMMs.
//  - raw fp32 fed to tf32 mma (HW truncation) -> byte-copy loads
//  - e3 W1 pre-scaled into scratch (A loads are raw gathers)
//  - mean_kernel split-K parallel; gate float4-vectorized
// GB300 ATS rule: no __device__ symbol passed from host.
// ============================================================

#define NB   16384
#define DD   512
#define NL   6
#define NCLS 3992
#define NE   4

#define BM 128
#define BN 64
#define BK 32
#define ASTR 36          // floats; 144B row stride (16B aligned)
#define BSTR 72          // floats; 288B row stride
#define STAGE (BM * ASTR + BK * BSTR)   // 6912 floats per stage
#define SMEM_BYTES (2 * STAGE * 4)      // 55296 B dynamic smem

// -------- device scratch --------
__device__ float g_h [NB * DD];
__device__ float g_s [NB * DD];
__device__ float g_td[NB * DD];
__device__ float g_mean[4096];
__device__ float g_w3[3072 * DD];    // pre-scaled e3_W1
__device__ int   g_sel[NB];
__device__ int   g_rows[NE * NB];
__device__ int   g_cnt[NE];

__device__ __forceinline__ uint32_t s2u(const void* p) {
    uint32_t a;
    asm("{ .reg .u64 t; cvta.to.shared.u64 t, %1; cvt.u32.u64 %0, t; }"
        : "=r"(a) : "l"(p));
    return a;
}

__device__ __forceinline__ void cp16(uint32_t dst, const void* src, int srcsz) {
    asm volatile("cp.async.cg.shared.global [%0], [%1], 16, %2;"
                 :: "r"(dst), "l"(src), "r"(srcsz));
}
__device__ __forceinline__ void cp_commit() { asm volatile("cp.async.commit_group;"); }
__device__ __forceinline__ void cp_wait0()  { asm volatile("cp.async.wait_group 0;" ::: "memory"); }

#define MMA_TF32(c, a, b)                                                    \
    asm("mma.sync.aligned.m16n8k8.row.col.f32.tf32.tf32.f32 "                \
        "{%0,%1,%2,%3}, {%4,%5,%6,%7}, {%8,%9}, {%0,%1,%2,%3};"              \
        : "+f"((c)[0]), "+f"((c)[1]), "+f"((c)[2]), "+f"((c)[3])             \
        : "r"((a)[0]), "r"((a)[1]), "r"((a)[2]), "r"((a)[3]),                \
          "r"((b)[0]), "r"((b)[1]))

// compute one BK=32 tile from a stage (4 k-steps of 8)
__device__ __forceinline__ void tile_mma(const float* As, const float* Bs,
                                         float acc[2][4][4],
                                         int warpM, int warpN, int g, int tg) {
    const unsigned* Au = (const unsigned*)As;
    const unsigned* Bu = (const unsigned*)Bs;
#pragma unroll
    for (int ks = 0; ks < 4; ks++) {
        unsigned a[2][4], b[4][2];
#pragma unroll
        for (int mi = 0; mi < 2; mi++) {
            int mb = warpM + mi * 16;
            a[mi][0] = Au[(mb + g) * ASTR + ks * 8 + tg];
            a[mi][1] = Au[(mb + g + 8) * ASTR + ks * 8 + tg];
            a[mi][2] = Au[(mb + g) * ASTR + ks * 8 + tg + 4];
            a[mi][3] = Au[(mb + g + 8) * ASTR + ks * 8 + tg + 4];
        }
#pragma unroll
        for (int ni = 0; ni < 4; ni++) {
            b[ni][0] = Bu[(ks * 8 + tg) * BSTR + warpN + ni * 8 + g];
            b[ni][1] = Bu[(ks * 8 + tg + 4) * BSTR + warpN + ni * 8 + g];
        }
#pragma unroll
        for (int mi = 0; mi < 2; mi++)
#pragma unroll
            for (int ni = 0; ni < 4; ni++)
                MMA_TF32(acc[mi][ni], a[mi], b[ni]);
    }
}

// ============================================================
// K1: gate logits + argmax (one warp per row), exact fp32
// ============================================================
__global__ __launch_bounds__(128) void gate_kernel(const float* __restrict__ fusion,
                                                   const float* __restrict__ gW,
                                                   const float* __restrict__ gb) {
    int warp = blockIdx.x * (blockDim.x >> 5) + (threadIdx.x >> 5);
    int lane = threadIdx.x & 31;
    if (warp >= NB) return;
    int b = warp;
    float a0 = 0.f, a1 = 0.f, a2 = 0.f, a3 = 0.f;
    for (int i4 = lane; i4 < (NL * DD) / 4; i4 += 32) {
        int kk = i4 * 4;
        int l = kk >> 9, d = kk & 511;
        float4 x = *(const float4*)(fusion + ((size_t)l * NB + b) * DD + d);
        float4 w0 = *(const float4*)(gW + (size_t)(kk + 0) * 4);
        float4 w1 = *(const float4*)(gW + (size_t)(kk + 1) * 4);
        float4 w2 = *(const float4*)(gW + (size_t)(kk + 2) * 4);
        float4 w3 = *(const float4*)(gW + (size_t)(kk + 3) * 4);
        a0 += x.x * w0.x + x.y * w1.x + x.z * w2.x + x.w * w3.x;
        a1 += x.x * w0.y + x.y * w1.y + x.z * w2.y + x.w * w3.y;
        a2 += x.x * w0.z + x.y * w1.z + x.z * w2.z + x.w * w3.z;
        a3 += x.x * w0.w + x.y * w1.w + x.z * w2.w + x.w * w3.w;
    }
#pragma unroll
    for (int o = 16; o; o >>= 1) {
        a0 += __shfl_down_sync(0xffffffffu, a0, o);
        a1 += __shfl_down_sync(0xffffffffu, a1, o);
        a2 += __shfl_down_sync(0xffffffffu, a2, o);
        a3 += __shfl_down_sync(0xffffffffu, a3, o);
    }
    if (lane == 0) {
        a0 += gb[0]; a1 += gb[1]; a2 += gb[2]; a3 += gb[3];
        int bi = 0; float best = a0;
        if (a1 > best) { best = a1; bi = 1; }
        if (a2 > best) { best = a2; bi = 2; }
        if (a3 > best) { best = a3; bi = 3; }
        g_sel[b] = bi;
    }
}

__global__ void zero_cnt_kernel() {
    if (threadIdx.x < NE) g_cnt[threadIdx.x] = 0;
}

__global__ void compact_kernel() {
    int b = blockIdx.x * blockDim.x + threadIdx.x;
    if (b < NB) {
        int e = g_sel[b];
        int i = atomicAdd(&g_cnt[e], 1);
        g_rows[e * NB + i] = b;
    }
}

// pre-scale e3_W1:  g_w3[k][c] = W[k][c] * (k<1536 ? a : b)
__global__ void scale_w3_kernel(const float* __restrict__ W,
                                const float* __restrict__ pa,
                                const float* __restrict__ pb) {
    int i = blockIdx.x * blockDim.x + threadIdx.x;
    if (i >= 3072 * DD) return;
    int k = i >> 9;
    g_w3[i] = W[i] * (k < 1536 ? *pa : *pb);
}

// mean: init with bias, then split-K partial colsums via atomics
__global__ void mean_init_kernel(const float* __restrict__ b) {
    int c = blockIdx.x * blockDim.x + threadIdx.x;
    if (c < NCLS) g_mean[c] = b[c];
}
__global__ void mean_part_kernel(const float* __restrict__ W) {
    int c = blockIdx.x * blockDim.x + threadIdx.x;
    if (c >= NCLS) return;
    int k0 = blockIdx.y * 64;
    float s = 0.f;
#pragma unroll 8
    for (int k = k0; k < k0 + 64; k++) s += W[(size_t)k * NCLS + c];
    atomicAdd(&g_mean[c], 0.5f * s);
}

// ============================================================
// K2: routed expert layer1, pipelined tf32 MMA
// ============================================================
__global__ __launch_bounds__(256) void expert1_mma(
    const float* __restrict__ fusion,
    const float* W10, const float* W11, const float* W12,
    const float* b10, const float* b11, const float* b12, const float* b13) {

    extern __shared__ float smem[];
    int e = blockIdx.z;
    int cnt = g_cnt[e];
    int row0 = blockIdx.x * BM;
    if (row0 >= cnt) return;

    int seg = 0;
#pragma unroll
    for (int q = 0; q < NE; q++) if (q < e) seg += g_cnt[q];

    const float* W1s[4] = { W10, W11, W12, g_w3 };
    const float* b1s[4] = { b10, b11, b12, b13 };
    const int    Ks[4]  = { 3 * DD, 3 * DD, 6 * DD, 6 * DD };
    const int    Bs_[4] = { 0, 3, 0, 0 };
    const float* W1 = W1s[e];
    const float* b1 = b1s[e];
    int K    = Ks[e];
    int base = Bs_[e];

    __shared__ int rowids[BM];
    int tid = threadIdx.x;
    for (int i = tid; i < BM; i += 256) {
        int r = row0 + i;
        rowids[i] = (r < cnt) ? g_rows[e * NB + r] : -1;
    }
    __syncthreads();

    int col0 = blockIdx.y * BN;
    int wid = tid >> 5, lane = tid & 31, g = lane >> 2, tg = lane & 3;
    int warpM = (wid & 3) * 32, warpN = (wid >> 2) * 32;

    // per-thread load coords
    int ar = tid >> 3, ak = (tid & 7) * 4;          // A: 4 chunks (ar+32t)
    int bk = tid >> 4, bn = (tid & 15) * 4;         // B: 2 chunks (bk+16t)

    float acc[2][4][4];
#pragma unroll
    for (int mi = 0; mi < 2; mi++)
#pragma unroll
        for (int ni = 0; ni < 4; ni++)
#pragma unroll
            for (int k = 0; k < 4; k++) acc[mi][ni][k] = 0.f;

    int ntiles = K / BK;

    // prefetch tile 0 into stage 0
    {
        float* As = smem;
        float* Bsm = smem + BM * ASTR;
#pragma unroll
        for (int t = 0; t < 4; t++) {
            int r = ar + t * 32;
            int row = rowids[r];
            int kg = ak;
            int lraw = kg >> 9, d = kg & 511;
            const float* src = fusion + ((size_t)(lraw + base) * NB + (row < 0 ? 0 : row)) * DD + d;
            cp16(s2u(&As[r * ASTR + ak]), src, row >= 0 ? 16 : 0);
        }
#pragma unroll
        for (int t = 0; t < 2; t++) {
            int kr = bk + t * 16;
            cp16(s2u(&Bsm[kr * BSTR + bn]), W1 + (size_t)kr * DD + col0 + bn, 16);
        }
        cp_commit();
    }

    for (int it = 0; it < ntiles; it++) {
        float* Ac = smem + (it & 1) * STAGE;
        float* Bc = Ac + BM * ASTR;
        cp_wait0();
        __syncthreads();

        if (it + 1 < ntiles) {
            int kc = (it + 1) * BK;
            float* An = smem + ((it + 1) & 1) * STAGE;
            float* Bn = An + BM * ASTR;
#pragma unroll
            for (int t = 0; t < 4; t++) {
                int r = ar + t * 32;
                int row = rowids[r];
                int kg = kc + ak;
                int lraw = kg >> 9, d = kg & 511;
                const float* src = fusion + ((size_t)(lraw + base) * NB + (row < 0 ? 0 : row)) * DD + d;
                cp16(s2u(&An[r * ASTR + ak]), src, row >= 0 ? 16 : 0);
            }
#pragma unroll
            for (int t = 0; t < 2; t++) {
                int kr = bk + t * 16;
                cp16(s2u(&Bn[kr * BSTR + bn]), W1 + (size_t)(kc + kr) * DD + col0 + bn, 16);
            }
            cp_commit();
        }

        tile_mma(Ac, Bc, acc, warpM, warpN, g, tg);
    }

#pragma unroll
    for (int mi = 0; mi < 2; mi++) {
        int ra = row0 + warpM + mi * 16 + g;
        int rb = ra + 8;
#pragma unroll
        for (int ni = 0; ni < 4; ni++) {
            int c0 = col0 + warpN + ni * 8 + tg * 2;
            int c1 = c0 + 1;
            float bb0 = b1[c0], bb1 = b1[c1];
            if (ra < cnt) {
                g_h[(size_t)(seg + ra) * DD + c0] = fmaxf(acc[mi][ni][0] + bb0, 0.f);
                g_h[(size_t)(seg + ra) * DD + c1] = fmaxf(acc[mi][ni][1] + bb1, 0.f);
            }
            if (rb < cnt) {
                g_h[(size_t)(seg + rb) * DD + c0] = fmaxf(acc[mi][ni][2] + bb0, 0.f);
                g_h[(size_t)(seg + rb) * DD + c1] = fmaxf(acc[mi][ni][3] + bb1, 0.f);
            }
        }
    }
}

// ============================================================
// K3: routed expert layer2, pipelined; scatter to g_s
// ============================================================
__global__ __launch_bounds__(256) void expert2_mma(
    const float* W20, const float* W21, const float* W22, const float* W23,
    const float* b20, const float* b21, const float* b22, const float* b23) {

    extern __shared__ float smem[];
    int e = blockIdx.z;
    int cnt = g_cnt[e];
    int row0 = blockIdx.x * BM;
    if (row0 >= cnt) return;

    int seg = 0;
#pragma unroll
    for (int q = 0; q < NE; q++) if (q < e) seg += g_cnt[q];

    const float* W2s[4] = { W20, W21, W22, W23 };
    const float* b2s[4] = { b20, b21, b22, b23 };
    const float* W2 = W2s[e];
    const float* b2 = b2s[e];

    __shared__ int rowids[BM];
    int tid = threadIdx.x;
    for (int i = tid; i < BM; i += 256) {
        int r = row0 + i;
        rowids[i] = (r < cnt) ? g_rows[e * NB + r] : -1;
    }
    __syncthreads();

    int col0 = blockIdx.y * BN;
    int wid = tid >> 5, lane = tid & 31, g = lane >> 2, tg = lane & 3;
    int warpM = (wid & 3) * 32, warpN = (wid >> 2) * 32;
    int ar = tid >> 3, ak = (tid & 7) * 4;
    int bk = tid >> 4, bn = (tid & 15) * 4;

    float acc[2][4][4];
#pragma unroll
    for (int mi = 0; mi < 2; mi++)
#pragma unroll
        for (int ni = 0; ni < 4; ni++)
#pragma unroll
            for (int k = 0; k < 4; k++) acc[mi][ni][k] = 0.f;

    const int ntiles = DD / BK;

    {
        float* As = smem;
        float* Bsm = smem + BM * ASTR;
#pragma unroll
        for (int t = 0; t < 4; t++) {
            int r = ar + t * 32;
            int ok = (row0 + r < cnt);
            cp16(s2u(&As[r * ASTR + ak]),
                 g_h + (size_t)(seg + row0 + r) * DD + ak, ok ? 16 : 0);
        }
#pragma unroll
        for (int t = 0; t < 2; t++) {
            int kr = bk + t * 16;
            cp16(s2u(&Bsm[kr * BSTR + bn]), W2 + (size_t)kr * DD + col0 + bn, 16);
        }
        cp_commit();
    }

    for (int it = 0; it < ntiles; it++) {
        float* Ac = smem + (it & 1) * STAGE;
        float* Bc = Ac + BM * ASTR;
        cp_wait0();
        __syncthreads();

        if (it + 1 < ntiles) {
            int kc = (it + 1) * BK;
            float* An = smem + ((it + 1) & 1) * STAGE;
            float* Bn = An + BM * ASTR;
#pragma unroll
            for (int t = 0; t < 4; t++) {
                int r = ar + t * 32;
                int ok = (row0 + r < cnt);
                cp16(s2u(&An[r * ASTR + ak]),
                     g_h + (size_t)(seg + row0 + r) * DD + kc + ak, ok ? 16 : 0);
            }
#pragma unroll
            for (int t = 0; t < 2; t++) {
                int kr = bk + t * 16;
                cp16(s2u(&Bn[kr * BSTR + bn]), W2 + (size_t)(kc + kr) * DD + col0 + bn, 16);
            }
            cp_commit();
        }

        tile_mma(Ac, Bc, acc, warpM, warpN, g, tg);
    }

#pragma unroll
    for (int mi = 0; mi < 2; mi++) {
        int la = warpM + mi * 16 + g;
        int lb = la + 8;
        int rowa = rowids[la];
        int rowb = rowids[lb];
#pragma unroll
        for (int ni = 0; ni < 4; ni++) {
            int c0 = col0 + warpN + ni * 8 + tg * 2;
            int c1 = c0 + 1;
            float bb0 = b2[c0], bb1 = b2[c1];
            if (rowa >= 0) {
                g_s[(size_t)rowa * DD + c0] = acc[mi][ni][0] + bb0;
                g_s[(size_t)rowa * DD + c1] = acc[mi][ni][1] + bb1;
            }
            if (rowb >= 0) {
                g_s[(size_t)rowb * DD + c0] = acc[mi][ni][2] + bb0;
                g_s[(size_t)rowb * DD + c1] = acc[mi][ni][3] + bb1;
            }
        }
    }
}

// ============================================================
// K4: decoder layer1, pipelined; store sigmoid-0.5
// ============================================================
__global__ __launch_bounds__(256) void dec1_mma(
    const float* __restrict__ W, const float* __restrict__ bias) {

    extern __shared__ float smem[];
    int row0 = blockIdx.x * BM;
    int col0 = blockIdx.y * BN;

    int tid = threadIdx.x;
    int wid = tid >> 5, lane = tid & 31, g = lane >> 2, tg = lane & 3;
    int warpM = (wid & 3) * 32, warpN = (wid >> 2) * 32;
    int ar = tid >> 3, ak = (tid & 7) * 4;
    int bk = tid >> 4, bn = (tid & 15) * 4;

    float acc[2][4][4];
#pragma unroll
    for (int mi = 0; mi < 2; mi++)
#pragma unroll
        for (int ni = 0; ni < 4; ni++)
#pragma unroll
            for (int k = 0; k < 4; k++) acc[mi][ni][k] = 0.f;

    const int ntiles = DD / BK;

    {
        float* As = smem;
        float* Bsm = smem + BM * ASTR;
#pragma unroll
        for (int t = 0; t < 4; t++) {
            int r = ar + t * 32;
            cp16(s2u(&As[r * ASTR + ak]), g_s + (size_t)(row0 + r) * DD + ak, 16);
        }
#pragma unroll
        for (int t = 0; t < 2; t++) {
            int kr = bk + t * 16;
            cp16(s2u(&Bsm[kr * BSTR + bn]), W + (size_t)kr * DD + col0 + bn, 16);
        }
        cp_commit();
    }

    for (int it = 0; it < ntiles; it++) {
        float* Ac = smem + (it & 1) * STAGE;
        float* Bc = Ac + BM * ASTR;
        cp_wait0();
        __syncthreads();

        if (it + 1 < ntiles) {
            int kc = (it + 1) * BK;
            float* An = smem + ((it + 1) & 1) * STAGE;
            float* Bn = An + BM * ASTR;
#pragma unroll
            for (int t = 0; t < 4; t++) {
                int r = ar + t * 32;
                cp16(s2u(&An[r * ASTR + ak]), g_s + (size_t)(row0 + r) * DD + kc + ak, 16);
            }
#pragma unroll
            for (int t = 0; t < 2; t++) {
                int kr = bk + t * 16;
                cp16(s2u(&Bn[kr * BSTR + bn]), W + (size_t)(kc + kr) * DD + col0 + bn, 16);
            }
            cp_commit();
        }

        tile_mma(Ac, Bc, acc, warpM, warpN, g, tg);
    }

#pragma unroll
    for (int mi = 0; mi < 2; mi++) {
        int ra = row0 + warpM + mi * 16 + g;
        int rb = ra + 8;
#pragma unroll
        for (int ni = 0; ni < 4; ni++) {
            int c0 = col0 + warpN + ni * 8 + tg * 2;
            int c1 = c0 + 1;
            float bb0 = bias[c0], bb1 = bias[c1];
            float z;
            z = acc[mi][ni][0] + bb0; g_td[(size_t)ra * DD + c0] = 1.f / (1.f + expf(-z)) - 0.5f;
            z = acc[mi][ni][1] + bb1; g_td[(size_t)ra * DD + c1] = 1.f / (1.f + expf(-z)) - 0.5f;
            z = acc[mi][ni][2] + bb0; g_td[(size_t)rb * DD + c0] = 1.f / (1.f + expf(-z)) - 0.5f;
            z = acc[mi][ni][3] + bb1; g_td[(size_t)rb * DD + c1] = 1.f / (1.f + expf(-z)) - 0.5f;
        }
    }
}

// ============================================================
// K5: decoder layer2 on delta; out = acc + mean[c]
// ============================================================
__global__ __launch_bounds__(256) void dec2_mma(
    const float* __restrict__ W, float* __restrict__ out) {

    extern __shared__ float smem[];
    int row0 = blockIdx.x * BM;
    int col0 = blockIdx.y * BN;

    int tid = threadIdx.x;
    int wid = tid >> 5, lane = tid & 31, g = lane >> 2, tg = lane & 3;
    int warpM = (wid & 3) * 32, warpN = (wid >> 2) * 32;
    int ar = tid >> 3, ak = (tid & 7) * 4;
    int bk = tid >> 4, bn = (tid & 15) * 4;

    float acc[2][4][4];
#pragma unroll
    for (int mi = 0; mi < 2; mi++)
#pragma unroll
        for (int ni = 0; ni < 4; ni++)
#pragma unroll
            for (int k = 0; k < 4; k++) acc[mi][ni][k] = 0.f;

    const int ntiles = DD / BK;
    int cfull = (col0 + bn + 4 <= NCLS) ? 16 : 0;

    {
        float* As = smem;
        float* Bsm = smem + BM * ASTR;
#pragma unroll
        for (int t = 0; t < 4; t++) {
            int r = ar + t * 32;
            cp16(s2u(&As[r * ASTR + ak]), g_td + (size_t)(row0 + r) * DD + ak, 16);
        }
#pragma unroll
        for (int t = 0; t < 2; t++) {
            int kr = bk + t * 16;
            cp16(s2u(&Bsm[kr * BSTR + bn]),
                 W + (size_t)kr * NCLS + col0 + bn, cfull);
        }
        cp_commit();
    }

    for (int it = 0; it < ntiles; it++) {
        float* Ac = smem + (it & 1) * STAGE;
        float* Bc = Ac + BM * ASTR;
        cp_wait0();
        __syncthreads();

        if (it + 1 < ntiles) {
            int kc = (it + 1) * BK;
            float* An = smem + ((it + 1) & 1) * STAGE;
            float* Bn = An + BM * ASTR;
#pragma unroll
            for (int t = 0; t < 4; t++) {
                int r = ar + t * 32;
                cp16(s2u(&An[r * ASTR + ak]), g_td + (size_t)(row0 + r) * DD + kc + ak, 16);
            }
#pragma unroll
            for (int t = 0; t < 2; t++) {
                int kr = bk + t * 16;
                cp16(s2u(&Bn[kr * BSTR + bn]),
                     W + (size_t)(kc + kr) * NCLS + col0 + bn, cfull);
            }
            cp_commit();
        }

        tile_mma(Ac, Bc, acc, warpM, warpN, g, tg);
    }

#pragma unroll
    for (int mi = 0; mi < 2; mi++) {
        int ra = row0 + warpM + mi * 16 + g;
        int rb = ra + 8;
#pragma unroll
        for (int ni = 0; ni < 4; ni++) {
            int c0 = col0 + warpN + ni * 8 + tg * 2;
            int c1 = c0 + 1;
            if (c0 < NCLS) {
                float m0 = g_mean[c0];
                out[(size_t)ra * NCLS + c0] = acc[mi][ni][0] + m0;
                out[(size_t)rb * NCLS + c0] = acc[mi][ni][2] + m0;
            }
            if (c1 < NCLS) {
                float m1 = g_mean[c1];
                out[(size_t)ra * NCLS + c1] = acc[mi][ni][1] + m1;
                out[(size_t)rb * NCLS + c1] = acc[mi][ni][3] + m1;
            }
        }
    }
}

// ============================================================
// launch
// ============================================================
extern "C" void kernel_launch(void* const* d_in, const int* in_sizes, int n_in,
                              void* d_out, int out_size) {
    const float* fusion = (const float*)d_in[0];
    const float* gate_W = (const float*)d_in[1];
    const float* gate_b = (const float*)d_in[2];
    const float* e0_W1  = (const float*)d_in[3];
    const float* e0_b1  = (const float*)d_in[4];
    const float* e0_W2  = (const float*)d_in[5];
    const float* e0_b2  = (const float*)d_in[6];
    const float* e1_W1  = (const float*)d_in[7];
    const float* e1_b1  = (const float*)d_in[8];
    const float* e1_W2  = (const float*)d_in[9];
    const float* e1_b2  = (const float*)d_in[10];
    const float* e2_W1  = (const float*)d_in[11];
    const float* e2_b1  = (const float*)d_in[12];
    const float* e2_W2  = (const float*)d_in[13];
    const float* e2_b2  = (const float*)d_in[14];
    const float* e3_W1  = (const float*)d_in[15];
    const float* e3_b1  = (const float*)d_in[16];
    const float* e3_W2  = (const float*)d_in[17];
    const float* e3_b2  = (const float*)d_in[18];
    const float* e3_a   = (const float*)d_in[19];
    const float* e3_b   = (const float*)d_in[20];
    const float* dec_W1 = (const float*)d_in[21];
    const float* dec_b1 = (const float*)d_in[22];
    const float* dec_W2 = (const float*)d_in[23];
    const float* dec_b2 = (const float*)d_in[24];
    float* out = (float*)d_out;

    static bool attr_done = false;
    if (!attr_done) {
        cudaFuncSetAttribute(expert1_mma, cudaFuncAttributeMaxDynamicSharedMemorySize, SMEM_BYTES);
        cudaFuncSetAttribute(expert2_mma, cudaFuncAttributeMaxDynamicSharedMemorySize, SMEM_BYTES);
        cudaFuncSetAttribute(dec1_mma,    cudaFuncAttributeMaxDynamicSharedMemorySize, SMEM_BYTES);
        cudaFuncSetAttribute(dec2_mma,    cudaFuncAttributeMaxDynamicSharedMemorySize, SMEM_BYTES);
        attr_done = true;
    }

    gate_kernel<<<NB / 4, 128>>>(fusion, gate_W, gate_b);
    zero_cnt_kernel<<<1, 32>>>();
    compact_kernel<<<NB / 256, 256>>>();
    scale_w3_kernel<<<(3072 * DD) / 256, 256>>>(e3_W1, e3_a, e3_b);
    mean_init_kernel<<<(NCLS + 255) / 256, 256>>>(dec_b2);
    {
        dim3 grid((NCLS + 255) / 256, DD / 64);
        mean_part_kernel<<<grid, 256>>>(dec_W2);
    }

    {
        dim3 grid(NB / BM, DD / BN, NE);
        expert1_mma<<<grid, 256, SMEM_BYTES>>>(fusion,
            e0_W1, e1_W1, e2_W1,
            e0_b1, e1_b1, e2_b1, e3_b1);
    }
    {
        dim3 grid(NB / BM, DD / BN, NE);
        expert2_mma<<<grid, 256, SMEM_BYTES>>>(
            e0_W2, e1_W2, e2_W2, e3_W2,
            e0_b2, e1_b2, e2_b2, e3_b2);
    }
    {
        dim3 grid(NB / BM, DD / BN);
        dec1_mma<<<grid, 256, SMEM_BYTES>>>(dec_W1, dec_b1);
    }
    {
        dim3 grid(NB / BM, (NCLS + BN - 1) / BN);
        dec2_mma<<<grid, 256, SMEM_BYTES>>>(dec_W2, out);
    }
}

// round 11
// speedup vs baseline: 9.5489x; 1.0486x over previous
#include <cuda_runtime.h>
#include <stdint.h>
#include <math.h>

// ============================================================
// ROUND 11: 128x128 tiles (was 128x64) — halve A-side L2 traffic,
// 2x MMA per sync. cp.async double-buffered tf32 MMA, raw-fp32
// operands (HW truncation). GB300 ATS rule: no __device__ symbol
// passed from host.
// ============================================================

#define NB   16384
#define DD   512
#define NL   6
#define NCLS 3992
#define NE   4

#define BM 128
#define BN 128
#define BK 32
#define ASTR 36            // A row stride (floats)
#define BSTR 136           // B row stride (floats)
#define STAGE (BM * ASTR + BK * BSTR)   // 8960 floats
#define SMEM_BYTES (2 * STAGE * 4)      // 71680 B

// -------- device scratch --------
__device__ float g_h [NB * DD];
__device__ float g_s [NB * DD];
__device__ float g_td[NB * DD];
__device__ float g_mean[4096];
__device__ float g_w3[3072 * DD];
__device__ int   g_sel[NB];
__device__ int   g_rows[NE * NB];
__device__ int   g_cnt[NE];

__device__ __forceinline__ uint32_t s2u(const void* p) {
    uint32_t a;
    asm("{ .reg .u64 t; cvta.to.shared.u64 t, %1; cvt.u32.u64 %0, t; }"
        : "=r"(a) : "l"(p));
    return a;
}
__device__ __forceinline__ void cp16(uint32_t dst, const void* src, int srcsz) {
    asm volatile("cp.async.cg.shared.global [%0], [%1], 16, %2;"
                 :: "r"(dst), "l"(src), "r"(srcsz));
}
__device__ __forceinline__ void cp_commit() { asm volatile("cp.async.commit_group;"); }
__device__ __forceinline__ void cp_wait0()  { asm volatile("cp.async.wait_group 0;" ::: "memory"); }

#define MMA_TF32(c, a, b)                                                    \
    asm("mma.sync.aligned.m16n8k8.row.col.f32.tf32.tf32.f32 "                \
        "{%0,%1,%2,%3}, {%4,%5,%6,%7}, {%8,%9}, {%0,%1,%2,%3};"              \
        : "+f"((c)[0]), "+f"((c)[1]), "+f"((c)[2]), "+f"((c)[3])             \
        : "r"((a)[0]), "r"((a)[1]), "r"((a)[2]), "r"((a)[3]),                \
          "r"((b)[0]), "r"((b)[1]))

// one BK=32 tile: warp covers 32(M) x 64(N); acc[2][8][4]
__device__ __forceinline__ void tile_mma(const float* As, const float* Bs,
                                         float acc[2][8][4],
                                         int warpM, int warpN, int g, int tg) {
    const unsigned* Au = (const unsigned*)As;
    const unsigned* Bu = (const unsigned*)Bs;
#pragma unroll
    for (int ks = 0; ks < 4; ks++) {
        unsigned a[2][4], b[8][2];
#pragma unroll
        for (int mi = 0; mi < 2; mi++) {
            int mb = warpM + mi * 16;
            a[mi][0] = Au[(mb + g) * ASTR + ks * 8 + tg];
            a[mi][1] = Au[(mb + g + 8) * ASTR + ks * 8 + tg];
            a[mi][2] = Au[(mb + g) * ASTR + ks * 8 + tg + 4];
            a[mi][3] = Au[(mb + g + 8) * ASTR + ks * 8 + tg + 4];
        }
#pragma unroll
        for (int ni = 0; ni < 8; ni++) {
            b[ni][0] = Bu[(ks * 8 + tg) * BSTR + warpN + ni * 8 + g];
            b[ni][1] = Bu[(ks * 8 + tg + 4) * BSTR + warpN + ni * 8 + g];
        }
#pragma unroll
        for (int mi = 0; mi < 2; mi++)
#pragma unroll
            for (int ni = 0; ni < 8; ni++)
                MMA_TF32(acc[mi][ni], a[mi], b[ni]);
    }
}

// ============================================================
// K1: gate logits + argmax (one warp per row), exact fp32
// ============================================================
__global__ __launch_bounds__(128) void gate_kernel(const float* __restrict__ fusion,
                                                   const float* __restrict__ gW,
                                                   const float* __restrict__ gb) {
    int warp = blockIdx.x * (blockDim.x >> 5) + (threadIdx.x >> 5);
    int lane = threadIdx.x & 31;
    if (warp >= NB) return;
    int b = warp;
    float a0 = 0.f, a1 = 0.f, a2 = 0.f, a3 = 0.f;
    for (int i4 = lane; i4 < (NL * DD) / 4; i4 += 32) {
        int kk = i4 * 4;
        int l = kk >> 9, d = kk & 511;
        float4 x = *(const float4*)(fusion + ((size_t)l * NB + b) * DD + d);
        float4 w0 = *(const float4*)(gW + (size_t)(kk + 0) * 4);
        float4 w1 = *(const float4*)(gW + (size_t)(kk + 1) * 4);
        float4 w2 = *(const float4*)(gW + (size_t)(kk + 2) * 4);
        float4 w3 = *(const float4*)(gW + (size_t)(kk + 3) * 4);
        a0 += x.x * w0.x + x.y * w1.x + x.z * w2.x + x.w * w3.x;
        a1 += x.x * w0.y + x.y * w1.y + x.z * w2.y + x.w * w3.y;
        a2 += x.x * w0.z + x.y * w1.z + x.z * w2.z + x.w * w3.z;
        a3 += x.x * w0.w + x.y * w1.w + x.z * w2.w + x.w * w3.w;
    }
#pragma unroll
    for (int o = 16; o; o >>= 1) {
        a0 += __shfl_down_sync(0xffffffffu, a0, o);
        a1 += __shfl_down_sync(0xffffffffu, a1, o);
        a2 += __shfl_down_sync(0xffffffffu, a2, o);
        a3 += __shfl_down_sync(0xffffffffu, a3, o);
    }
    if (lane == 0) {
        a0 += gb[0]; a1 += gb[1]; a2 += gb[2]; a3 += gb[3];
        int bi = 0; float best = a0;
        if (a1 > best) { best = a1; bi = 1; }
        if (a2 > best) { best = a2; bi = 2; }
        if (a3 > best) { best = a3; bi = 3; }
        g_sel[b] = bi;
    }
}

__global__ void zero_cnt_kernel() {
    if (threadIdx.x < NE) g_cnt[threadIdx.x] = 0;
}
__global__ void compact_kernel() {
    int b = blockIdx.x * blockDim.x + threadIdx.x;
    if (b < NB) {
        int e = g_sel[b];
        int i = atomicAdd(&g_cnt[e], 1);
        g_rows[e * NB + i] = b;
    }
}
__global__ void scale_w3_kernel(const float* __restrict__ W,
                                const float* __restrict__ pa,
                                const float* __restrict__ pb) {
    int i = blockIdx.x * blockDim.x + threadIdx.x;
    if (i >= 3072 * DD) return;
    int k = i >> 9;
    g_w3[i] = W[i] * (k < 1536 ? *pa : *pb);
}
__global__ void mean_init_kernel(const float* __restrict__ b) {
    int c = blockIdx.x * blockDim.x + threadIdx.x;
    if (c < NCLS) g_mean[c] = b[c];
}
__global__ void mean_part_kernel(const float* __restrict__ W) {
    int c = blockIdx.x * blockDim.x + threadIdx.x;
    if (c >= NCLS) return;
    int k0 = blockIdx.y * 64;
    float s = 0.f;
#pragma unroll 8
    for (int k = k0; k < k0 + 64; k++) s += W[(size_t)k * NCLS + c];
    atomicAdd(&g_mean[c], 0.5f * s);
}

// ============================================================
// K2: routed expert layer1, pipelined tf32 MMA (128x128)
// ============================================================
__global__ __launch_bounds__(256) void expert1_mma(
    const float* __restrict__ fusion,
    const float* W10, const float* W11, const float* W12,
    const float* b10, const float* b11, const float* b12, const float* b13) {

    extern __shared__ float smem[];
    int e = blockIdx.z;
    int cnt = g_cnt[e];
    int row0 = blockIdx.x * BM;
    if (row0 >= cnt) return;

    int seg = 0;
#pragma unroll
    for (int q = 0; q < NE; q++) if (q < e) seg += g_cnt[q];

    const float* W1s[4] = { W10, W11, W12, g_w3 };
    const float* b1s[4] = { b10, b11, b12, b13 };
    const int    Ks[4]  = { 3 * DD, 3 * DD, 6 * DD, 6 * DD };
    const int    Bs_[4] = { 0, 3, 0, 0 };
    const float* W1 = W1s[e];
    const float* b1 = b1s[e];
    int K    = Ks[e];
    int base = Bs_[e];

    __shared__ int rowids[BM];
    int tid = threadIdx.x;
    for (int i = tid; i < BM; i += 256) {
        int r = row0 + i;
        rowids[i] = (r < cnt) ? g_rows[e * NB + r] : -1;
    }
    __syncthreads();

    int col0 = blockIdx.y * BN;
    int wid = tid >> 5, lane = tid & 31, g = lane >> 2, tg = lane & 3;
    int warpM = (wid & 3) * 32, warpN = (wid >> 2) * 64;
    int ar = tid >> 3, ak = (tid & 7) * 4;          // A: 4 chunks (ar+32t)
    // B: 4 chunks: q=tid+t*256 -> bk=q>>5 (0..31), bn=(q&31)*4

    float acc[2][8][4];
#pragma unroll
    for (int mi = 0; mi < 2; mi++)
#pragma unroll
        for (int ni = 0; ni < 8; ni++)
#pragma unroll
            for (int k = 0; k < 4; k++) acc[mi][ni][k] = 0.f;

    int ntiles = K / BK;

    {
        float* As = smem;
        float* Bsm = smem + BM * ASTR;
#pragma unroll
        for (int t = 0; t < 4; t++) {
            int r = ar + t * 32;
            int row = rowids[r];
            int lraw = ak >> 9, d = ak & 511;
            const float* src = fusion + ((size_t)(lraw + base) * NB + (row < 0 ? 0 : row)) * DD + d;
            cp16(s2u(&As[r * ASTR + ak]), src, row >= 0 ? 16 : 0);
        }
#pragma unroll
        for (int t = 0; t < 4; t++) {
            int q = tid + t * 256;
            int bk = q >> 5, bn = (q & 31) * 4;
            cp16(s2u(&Bsm[bk * BSTR + bn]), W1 + (size_t)bk * DD + col0 + bn, 16);
        }
        cp_commit();
    }

    for (int it = 0; it < ntiles; it++) {
        float* Ac = smem + (it & 1) * STAGE;
        float* Bc = Ac + BM * ASTR;
        cp_wait0();
        __syncthreads();

        if (it + 1 < ntiles) {
            int kc = (it + 1) * BK;
            float* An = smem + ((it + 1) & 1) * STAGE;
            float* Bn = An + BM * ASTR;
#pragma unroll
            for (int t = 0; t < 4; t++) {
                int r = ar + t * 32;
                int row = rowids[r];
                int kg = kc + ak;
                int lraw = kg >> 9, d = kg & 511;
                const float* src = fusion + ((size_t)(lraw + base) * NB + (row < 0 ? 0 : row)) * DD + d;
                cp16(s2u(&An[r * ASTR + ak]), src, row >= 0 ? 16 : 0);
            }
#pragma unroll
            for (int t = 0; t < 4; t++) {
                int q = tid + t * 256;
                int bk = q >> 5, bn = (q & 31) * 4;
                cp16(s2u(&Bn[bk * BSTR + bn]), W1 + (size_t)(kc + bk) * DD + col0 + bn, 16);
            }
            cp_commit();
        }

        tile_mma(Ac, Bc, acc, warpM, warpN, g, tg);
    }

#pragma unroll
    for (int mi = 0; mi < 2; mi++) {
        int ra = row0 + warpM + mi * 16 + g;
        int rb = ra + 8;
#pragma unroll
        for (int ni = 0; ni < 8; ni++) {
            int c0 = col0 + warpN + ni * 8 + tg * 2;
            int c1 = c0 + 1;
            float bb0 = b1[c0], bb1 = b1[c1];
            if (ra < cnt) {
                g_h[(size_t)(seg + ra) * DD + c0] = fmaxf(acc[mi][ni][0] + bb0, 0.f);
                g_h[(size_t)(seg + ra) * DD + c1] = fmaxf(acc[mi][ni][1] + bb1, 0.f);
            }
            if (rb < cnt) {
                g_h[(size_t)(seg + rb) * DD + c0] = fmaxf(acc[mi][ni][2] + bb0, 0.f);
                g_h[(size_t)(seg + rb) * DD + c1] = fmaxf(acc[mi][ni][3] + bb1, 0.f);
            }
        }
    }
}

// ============================================================
// K3: routed expert layer2, pipelined; scatter to g_s
// ============================================================
__global__ __launch_bounds__(256) void expert2_mma(
    const float* W20, const float* W21, const float* W22, const float* W23,
    const float* b20, const float* b21, const float* b22, const float* b23) {

    extern __shared__ float smem[];
    int e = blockIdx.z;
    int cnt = g_cnt[e];
    int row0 = blockIdx.x * BM;
    if (row0 >= cnt) return;

    int seg = 0;
#pragma unroll
    for (int q = 0; q < NE; q++) if (q < e) seg += g_cnt[q];

    const float* W2s[4] = { W20, W21, W22, W23 };
    const float* b2s[4] = { b20, b21, b22, b23 };
    const float* W2 = W2s[e];
    const float* b2 = b2s[e];

    __shared__ int rowids[BM];
    int tid = threadIdx.x;
    for (int i = tid; i < BM; i += 256) {
        int r = row0 + i;
        rowids[i] = (r < cnt) ? g_rows[e * NB + r] : -1;
    }
    __syncthreads();

    int col0 = blockIdx.y * BN;
    int wid = tid >> 5, lane = tid & 31, g = lane >> 2, tg = lane & 3;
    int warpM = (wid & 3) * 32, warpN = (wid >> 2) * 64;
    int ar = tid >> 3, ak = (tid & 7) * 4;

    float acc[2][8][4];
#pragma unroll
    for (int mi = 0; mi < 2; mi++)
#pragma unroll
        for (int ni = 0; ni < 8; ni++)
#pragma unroll
            for (int k = 0; k < 4; k++) acc[mi][ni][k] = 0.f;

    const int ntiles = DD / BK;

    {
        float* As = smem;
        float* Bsm = smem + BM * ASTR;
#pragma unroll
        for (int t = 0; t < 4; t++) {
            int r = ar + t * 32;
            int ok = (row0 + r < cnt);
            cp16(s2u(&As[r * ASTR + ak]),
                 g_h + (size_t)(seg + row0 + r) * DD + ak, ok ? 16 : 0);
        }
#pragma unroll
        for (int t = 0; t < 4; t++) {
            int q = tid + t * 256;
            int bk = q >> 5, bn = (q & 31) * 4;
            cp16(s2u(&Bsm[bk * BSTR + bn]), W2 + (size_t)bk * DD + col0 + bn, 16);
        }
        cp_commit();
    }

    for (int it = 0; it < ntiles; it++) {
        float* Ac = smem + (it & 1) * STAGE;
        float* Bc = Ac + BM * ASTR;
        cp_wait0();
        __syncthreads();

        if (it + 1 < ntiles) {
            int kc = (it + 1) * BK;
            float* An = smem + ((it + 1) & 1) * STAGE;
            float* Bn = An + BM * ASTR;
#pragma unroll
            for (int t = 0; t < 4; t++) {
                int r = ar + t * 32;
                int ok = (row0 + r < cnt);
                cp16(s2u(&An[r * ASTR + ak]),
                     g_h + (size_t)(seg + row0 + r) * DD + kc + ak, ok ? 16 : 0);
            }
#pragma unroll
            for (int t = 0; t < 4; t++) {
                int q = tid + t * 256;
                int bk = q >> 5, bn = (q & 31) * 4;
                cp16(s2u(&Bn[bk * BSTR + bn]), W2 + (size_t)(kc + bk) * DD + col0 + bn, 16);
            }
            cp_commit();
        }

        tile_mma(Ac, Bc, acc, warpM, warpN, g, tg);
    }

#pragma unroll
    for (int mi = 0; mi < 2; mi++) {
        int la = warpM + mi * 16 + g;
        int lb = la + 8;
        int rowa = rowids[la];
        int rowb = rowids[lb];
#pragma unroll
        for (int ni = 0; ni < 8; ni++) {
            int c0 = col0 + warpN + ni * 8 + tg * 2;
            int c1 = c0 + 1;
            float bb0 = b2[c0], bb1 = b2[c1];
            if (rowa >= 0) {
                g_s[(size_t)rowa * DD + c0] = acc[mi][ni][0] + bb0;
                g_s[(size_t)rowa * DD + c1] = acc[mi][ni][1] + bb1;
            }
            if (rowb >= 0) {
                g_s[(size_t)rowb * DD + c0] = acc[mi][ni][2] + bb0;
                g_s[(size_t)rowb * DD + c1] = acc[mi][ni][3] + bb1;
            }
        }
    }
}

// ============================================================
// K4: decoder layer1; store sigmoid-0.5
// ============================================================
__global__ __launch_bounds__(256) void dec1_mma(
    const float* __restrict__ W, const float* __restrict__ bias) {

    extern __shared__ float smem[];
    int row0 = blockIdx.x * BM;
    int col0 = blockIdx.y * BN;

    int tid = threadIdx.x;
    int wid = tid >> 5, lane = tid & 31, g = lane >> 2, tg = lane & 3;
    int warpM = (wid & 3) * 32, warpN = (wid >> 2) * 64;
    int ar = tid >> 3, ak = (tid & 7) * 4;

    float acc[2][8][4];
#pragma unroll
    for (int mi = 0; mi < 2; mi++)
#pragma unroll
        for (int ni = 0; ni < 8; ni++)
#pragma unroll
            for (int k = 0; k < 4; k++) acc[mi][ni][k] = 0.f;

    const int ntiles = DD / BK;

    {
        float* As = smem;
        float* Bsm = smem + BM * ASTR;
#pragma unroll
        for (int t = 0; t < 4; t++) {
            int r = ar + t * 32;
            cp16(s2u(&As[r * ASTR + ak]), g_s + (size_t)(row0 + r) * DD + ak, 16);
        }
#pragma unroll
        for (int t = 0; t < 4; t++) {
            int q = tid + t * 256;
            int bk = q >> 5, bn = (q & 31) * 4;
            cp16(s2u(&Bsm[bk * BSTR + bn]), W + (size_t)bk * DD + col0 + bn, 16);
        }
        cp_commit();
    }

    for (int it = 0; it < ntiles; it++) {
        float* Ac = smem + (it & 1) * STAGE;
        float* Bc = Ac + BM * ASTR;
        cp_wait0();
        __syncthreads();

        if (it + 1 < ntiles) {
            int kc = (it + 1) * BK;
            float* An = smem + ((it + 1) & 1) * STAGE;
            float* Bn = An + BM * ASTR;
#pragma unroll
            for (int t = 0; t < 4; t++) {
                int r = ar + t * 32;
                cp16(s2u(&An[r * ASTR + ak]), g_s + (size_t)(row0 + r) * DD + kc + ak, 16);
            }
#pragma unroll
            for (int t = 0; t < 4; t++) {
                int q = tid + t * 256;
                int bk = q >> 5, bn = (q & 31) * 4;
                cp16(s2u(&Bn[bk * BSTR + bn]), W + (size_t)(kc + bk) * DD + col0 + bn, 16);
            }
            cp_commit();
        }

        tile_mma(Ac, Bc, acc, warpM, warpN, g, tg);
    }

#pragma unroll
    for (int mi = 0; mi < 2; mi++) {
        int ra = row0 + warpM + mi * 16 + g;
        int rb = ra + 8;
#pragma unroll
        for (int ni = 0; ni < 8; ni++) {
            int c0 = col0 + warpN + ni * 8 + tg * 2;
            int c1 = c0 + 1;
            float bb0 = bias[c0], bb1 = bias[c1];
            float z;
            z = acc[mi][ni][0] + bb0; g_td[(size_t)ra * DD + c0] = 1.f / (1.f + expf(-z)) - 0.5f;
            z = acc[mi][ni][1] + bb1; g_td[(size_t)ra * DD + c1] = 1.f / (1.f + expf(-z)) - 0.5f;
            z = acc[mi][ni][2] + bb0; g_td[(size_t)rb * DD + c0] = 1.f / (1.f + expf(-z)) - 0.5f;
            z = acc[mi][ni][3] + bb1; g_td[(size_t)rb * DD + c1] = 1.f / (1.f + expf(-z)) - 0.5f;
        }
    }
}

// ============================================================
// K5: decoder layer2 on delta; out = acc + mean[c]
// ============================================================
__global__ __launch_bounds__(256) void dec2_mma(
    const float* __restrict__ W, float* __restrict__ out) {

    extern __shared__ float smem[];
    int row0 = blockIdx.x * BM;
    int col0 = blockIdx.y * BN;

    int tid = threadIdx.x;
    int wid = tid >> 5, lane = tid & 31, g = lane >> 2, tg = lane & 3;
    int warpM = (wid & 3) * 32, warpN = (wid >> 2) * 64;
    int ar = tid >> 3, ak = (tid & 7) * 4;

    float acc[2][8][4];
#pragma unroll
    for (int mi = 0; mi < 2; mi++)
#pragma unroll
        for (int ni = 0; ni < 8; ni++)
#pragma unroll
            for (int k = 0; k < 4; k++) acc[mi][ni][k] = 0.f;

    const int ntiles = DD / BK;

    {
        float* As = smem;
        float* Bsm = smem + BM * ASTR;
#pragma unroll
        for (int t = 0; t < 4; t++) {
            int r = ar + t * 32;
            cp16(s2u(&As[r * ASTR + ak]), g_td + (size_t)(row0 + r) * DD + ak, 16);
        }
#pragma unroll
        for (int t = 0; t < 4; t++) {
            int q = tid + t * 256;
            int bk = q >> 5, bn = (q & 31) * 4;
            int c = col0 + bn;
            cp16(s2u(&Bsm[bk * BSTR + bn]),
                 W + (size_t)bk * NCLS + c, (c + 4 <= NCLS) ? 16 : 0);
        }
        cp_commit();
    }

    for (int it = 0; it < ntiles; it++) {
        float* Ac = smem + (it & 1) * STAGE;
        float* Bc = Ac + BM * ASTR;
        cp_wait0();
        __syncthreads();

        if (it + 1 < ntiles) {
            int kc = (it + 1) * BK;
            float* An = smem + ((it + 1) & 1) * STAGE;
            float* Bn = An + BM * ASTR;
#pragma unroll
            for (int t = 0; t < 4; t++) {
                int r = ar + t * 32;
                cp16(s2u(&An[r * ASTR + ak]), g_td + (size_t)(row0 + r) * DD + kc + ak, 16);
            }
#pragma unroll
            for (int t = 0; t < 4; t++) {
                int q = tid + t * 256;
                int bk = q >> 5, bn = (q & 31) * 4;
                int c = col0 + bn;
                cp16(s2u(&Bn[bk * BSTR + bn]),
                     W + (size_t)(kc + bk) * NCLS + c, (c + 4 <= NCLS) ? 16 : 0);
            }
            cp_commit();
        }

        tile_mma(Ac, Bc, acc, warpM, warpN, g, tg);
    }

#pragma unroll
    for (int mi = 0; mi < 2; mi++) {
        int ra = row0 + warpM + mi * 16 + g;
        int rb = ra + 8;
#pragma unroll
        for (int ni = 0; ni < 8; ni++) {
            int c0 = col0 + warpN + ni * 8 + tg * 2;
            int c1 = c0 + 1;
            if (c0 < NCLS) {
                float m0 = g_mean[c0];
                out[(size_t)ra * NCLS + c0] = acc[mi][ni][0] + m0;
                out[(size_t)rb * NCLS + c0] = acc[mi][ni][2] + m0;
            }
            if (c1 < NCLS) {
                float m1 = g_mean[c1];
                out[(size_t)ra * NCLS + c1] = acc[mi][ni][1] + m1;
                out[(size_t)rb * NCLS + c1] = acc[mi][ni][3] + m1;
            }
        }
    }
}

// ============================================================
// launch
// ============================================================
extern "C" void kernel_launch(void* const* d_in, const int* in_sizes, int n_in,
                              void* d_out, int out_size) {
    const float* fusion = (const float*)d_in[0];
    const float* gate_W = (const float*)d_in[1];
    const float* gate_b = (const float*)d_in[2];
    const float* e0_W1  = (const float*)d_in[3];
    const float* e0_b1  = (const float*)d_in[4];
    const float* e0_W2  = (const float*)d_in[5];
    const float* e0_b2  = (const float*)d_in[6];
    const float* e1_W1  = (const float*)d_in[7];
    const float* e1_b1  = (const float*)d_in[8];
    const float* e1_W2  = (const float*)d_in[9];
    const float* e1_b2  = (const float*)d_in[10];
    const float* e2_W1  = (const float*)d_in[11];
    const float* e2_b1  = (const float*)d_in[12];
    const float* e2_W2  = (const float*)d_in[13];
    const float* e2_b2  = (const float*)d_in[14];
    const float* e3_W1  = (const float*)d_in[15];
    const float* e3_b1  = (const float*)d_in[16];
    const float* e3_W2  = (const float*)d_in[17];
    const float* e3_b2  = (const float*)d_in[18];
    const float* e3_a   = (const float*)d_in[19];
    const float* e3_b   = (const float*)d_in[20];
    const float* dec_W1 = (const float*)d_in[21];
    const float* dec_b1 = (const float*)d_in[22];
    const float* dec_W2 = (const float*)d_in[23];
    const float* dec_b2 = (const float*)d_in[24];
    float* out = (float*)d_out;

    static bool attr_done = false;
    if (!attr_done) {
        cudaFuncSetAttribute(expert1_mma, cudaFuncAttributeMaxDynamicSharedMemorySize, SMEM_BYTES);
        cudaFuncSetAttribute(expert2_mma, cudaFuncAttributeMaxDynamicSharedMemorySize, SMEM_BYTES);
        cudaFuncSetAttribute(dec1_mma,    cudaFuncAttributeMaxDynamicSharedMemorySize, SMEM_BYTES);
        cudaFuncSetAttribute(dec2_mma,    cudaFuncAttributeMaxDynamicSharedMemorySize, SMEM_BYTES);
        attr_done = true;
    }

    gate_kernel<<<NB / 4, 128>>>(fusion, gate_W, gate_b);
    zero_cnt_kernel<<<1, 32>>>();
    compact_kernel<<<NB / 256, 256>>>();
    scale_w3_kernel<<<(3072 * DD) / 256, 256>>>(e3_W1, e3_a, e3_b);
    mean_init_kernel<<<(NCLS + 255) / 256, 256>>>(dec_b2);
    {
        dim3 grid((NCLS + 255) / 256, DD / 64);
        mean_part_kernel<<<grid, 256>>>(dec_W2);
    }

    {
        dim3 grid(NB / BM, DD / BN, NE);
        expert1_mma<<<grid, 256, SMEM_BYTES>>>(fusion,
            e0_W1, e1_W1, e2_W1,
            e0_b1, e1_b1, e2_b1, e3_b1);
    }
    {
        dim3 grid(NB / BM, DD / BN, NE);
        expert2_mma<<<grid, 256, SMEM_BYTES>>>(
            e0_W2, e1_W2, e2_W2, e3_W2,
            e0_b2, e1_b2, e2_b2, e3_b2);
    }
    {
        dim3 grid(NB / BM, DD / BN);
        dec1_mma<<<grid, 256, SMEM_BYTES>>>(dec_W1, dec_b1);
    }
    {
        dim3 grid(NB / BM, (NCLS + BN - 1) / BN);
        dec2_mma<<<grid, 256, SMEM_BYTES>>>(dec_W2, out);
    }
}